// round 3
// baseline (speedup 1.0000x reference)
#include <cuda_runtime.h>
#include <math.h>

#define TOTAL 16777216   // 8*512*64*64
#define PI_D 3.14159265358979323846

// ---------------- device scratch (no allocations allowed) ----------------
__device__ float g_Ac[64*64];
__device__ float g_Ak[512*512];
__device__ float g_AkT[512*512];
__device__ float g_W1T[4*512*128];       // [j][c][o]
__device__ float g_W2T[4*9*128*128];     // [j][tap][c][o]
__device__ float g_W3T[4*128*128];       // [j][c][o]
__device__ float g_T[TOTAL];             // after MN DCT  [b][c][mn]
__device__ float g_D[TOTAL];             // after C DCT   [b][k][mn]
__device__ float g_Y[TOTAL];             // masked inv-C  [b][c][mn]
__device__ float g_R[TOTAL];             // recon         [b][c][mn]
__device__ float g_H1[8*128*4096];
__device__ float g_H2[8*128*4096];
__device__ float g_OUTS[TOTAL];          // [j][b][o][mn]
__device__ unsigned g_hist[1024];        // 4 x 256
__device__ unsigned g_prefix[4];
__device__ unsigned g_remain[4];
__device__ float    g_thr[4];

// ---------------- init (runs every launch: deterministic graph replay) ----------------
__global__ void k_init() {
    int t = threadIdx.x;
    if (t < 4) {
        g_prefix[t] = 0u;
        g_remain[t] = (unsigned)(TOTAL >> (2 + 2*t));   // total/4, /16, /64, /256
    }
    for (int i = t; i < 1024; i += blockDim.x) g_hist[i] = 0u;
}

// ---------------- DCT basis matrices ----------------
__global__ void k_build_mats() {
    int tid = blockIdx.x * blockDim.x + threadIdx.x;
    if (tid < 512*512) {
        int k = tid >> 9, c = tid & 511;
        double v = cos((double)k * ((double)c + 0.5) * (PI_D/512.0)) * sqrt(2.0/512.0);
        if (k == 0) v *= 0.70710678118654752440;
        float f = (float)v;
        g_Ak[k*512 + c]  = f;
        g_AkT[c*512 + k] = f;
    }
    if (tid < 4096) {
        int k = tid >> 6, n = tid & 63;
        double v = cos((double)k * ((double)n + 0.5) * (PI_D/64.0)) * sqrt(2.0/64.0);
        if (k == 0) v *= 0.70710678118654752440;
        g_Ac[tid] = (float)v;
    }
}

// ---------------- weight transposes to K-major ----------------
__global__ void k_w1t(const float* __restrict__ W1) {   // [4][128][512] -> [4][512][128]
    int idx = blockIdx.x * blockDim.x + threadIdx.x;
    if (idx >= 4*128*512) return;
    int j = idx >> 16;
    int r = idx & 65535;
    int o = r >> 9, c = r & 511;
    g_W1T[j*65536 + c*128 + o] = W1[idx];
}
__global__ void k_w2t(const float* __restrict__ W2) {   // [4][128][128][3][3] -> [4][9][128][128] (tap,c,o)
    int idx = blockIdx.x * blockDim.x + threadIdx.x;
    if (idx >= 4*128*128*9) return;
    int tap = idx % 9;
    int r = idx / 9;
    int c = r & 127; r >>= 7;
    int o = r & 127; int j = r >> 7;
    g_W2T[((j*9 + tap)*128 + c)*128 + o] = W2[idx];
}
__global__ void k_w3t(const float* __restrict__ W3) {   // [4][128][128] -> [4][128][128] transposed
    int idx = blockIdx.x * blockDim.x + threadIdx.x;
    if (idx >= 4*128*128) return;
    int j = idx >> 14;
    int r = idx & 16383;
    int o = r >> 7, c = r & 127;
    g_W3T[j*16384 + c*128 + o] = W3[idx];
}

// ---------------- fused 64x64 two-sided DCT ----------------
// INV=0: out = A * X * A^T     INV=1: out = A^T * X * A
template<int INV>
__global__ __launch_bounds__(256) void k_dct64(const float* __restrict__ in, float* __restrict__ out) {
    __shared__ float sA[64*65];
    __shared__ float sX[64*65];
    const int tid = threadIdx.x;
    const float* __restrict__ src = in + (size_t)blockIdx.x * 4096;
    float* __restrict__ dst = out + (size_t)blockIdx.x * 4096;
    #pragma unroll
    for (int q = 0; q < 16; q++) {
        int e = tid + 256*q;
        int i = e >> 6, c = e & 63;
        sA[i*65 + c] = g_Ac[e];
        sX[i*65 + c] = src[e];
    }
    __syncthreads();
    const int i0 = (tid >> 4) << 2;
    const int j0 = (tid & 15) << 2;
    // stage 1: Q = (INV? A^T : A) * X
    float q1[4][4];
    #pragma unroll
    for (int a = 0; a < 4; a++)
        #pragma unroll
        for (int b = 0; b < 4; b++) q1[a][b] = 0.f;
    for (int k = 0; k < 64; k++) {
        float av[4], bv[4];
        #pragma unroll
        for (int a = 0; a < 4; a++)
            av[a] = INV ? sA[k*65 + i0 + a] : sA[(i0 + a)*65 + k];
        #pragma unroll
        for (int b = 0; b < 4; b++) bv[b] = sX[k*65 + j0 + b];
        #pragma unroll
        for (int a = 0; a < 4; a++)
            #pragma unroll
            for (int b = 0; b < 4; b++) q1[a][b] = fmaf(av[a], bv[b], q1[a][b]);
    }
    __syncthreads();
    // write Q into sX (X no longer needed)
    #pragma unroll
    for (int a = 0; a < 4; a++)
        #pragma unroll
        for (int b = 0; b < 4; b++) sX[(i0 + a)*65 + j0 + b] = q1[a][b];
    __syncthreads();
    // stage 2: out = Q * (INV? A : A^T)
    float q2[4][4];
    #pragma unroll
    for (int a = 0; a < 4; a++)
        #pragma unroll
        for (int b = 0; b < 4; b++) q2[a][b] = 0.f;
    for (int k = 0; k < 64; k++) {
        float av[4], bv[4];
        #pragma unroll
        for (int a = 0; a < 4; a++) av[a] = sX[(i0 + a)*65 + k];
        #pragma unroll
        for (int b = 0; b < 4; b++)
            bv[b] = INV ? sA[k*65 + j0 + b] : sA[(j0 + b)*65 + k];
        #pragma unroll
        for (int a = 0; a < 4; a++)
            #pragma unroll
            for (int b = 0; b < 4; b++) q2[a][b] = fmaf(av[a], bv[b], q2[a][b]);
    }
    #pragma unroll
    for (int a = 0; a < 4; a++) {
        float4 v = make_float4(q2[a][0], q2[a][1], q2[a][2], q2[a][3]);
        *(float4*)&dst[(i0 + a)*64 + j0] = v;
    }
}

// ---------------- generic tiled SGEMM: C[m][n] = sum_k A[k][m] * B[k][n] ----------------
// A is K-major [K][M]. B is [K][4096] (per-z batch slice). N fixed 4096.
// MASKED: B element zeroed when |v| < g_thr[branch]
// IM2COL: B row k maps to (tap = k>>7, c = k&127) with dilation-2 shifted spatial read from [128][4096]
// RELU: epilogue out = max(acc + bias[m], 0)
template<int MASKED, int IM2COL, int RELU>
__global__ __launch_bounds__(256) void k_gemm(
    const float* __restrict__ A, int lda,
    const float* __restrict__ Bbase, long strideB,
    float* __restrict__ Cbase, long strideC,
    int K, const float* __restrict__ bias, int branch)
{
    __shared__ float sA[8][128];
    __shared__ float sB[8][132];
    const float* __restrict__ B = Bbase + (long)blockIdx.z * strideB;
    float* __restrict__ C = Cbase + (long)blockIdx.z * strideC;
    const int m0 = blockIdx.y << 7;
    const int n0 = blockIdx.x << 7;
    const int tid = threadIdx.x;
    const int tx = tid & 15, ty = tid >> 4;
    const int lkk = tid >> 5, lcc = (tid & 31) << 2;
    float thr = 0.f;
    if (MASKED) thr = g_thr[branch];
    float acc[8][8];
    #pragma unroll
    for (int i = 0; i < 8; i++)
        #pragma unroll
        for (int j = 0; j < 8; j++) acc[i][j] = 0.f;

    for (int k0 = 0; k0 < K; k0 += 8) {
        // A tile
        float4 av = *(const float4*)&A[(size_t)(k0 + lkk) * lda + m0 + lcc];
        *(float4*)&sA[lkk][lcc] = av;
        // B tile
        if (!IM2COL) {
            float4 bv = *(const float4*)&B[(size_t)(k0 + lkk) * 4096 + n0 + lcc];
            if (MASKED) {
                bv.x = (fabsf(bv.x) >= thr) ? bv.x : 0.f;
                bv.y = (fabsf(bv.y) >= thr) ? bv.y : 0.f;
                bv.z = (fabsf(bv.z) >= thr) ? bv.z : 0.f;
                bv.w = (fabsf(bv.w) >= thr) ? bv.w : 0.f;
            }
            *(float4*)&sB[lkk][lcc] = bv;
        } else {
            int tap = k0 >> 7;                 // constant within the 8-row tile (8 | 128)
            int dy = 2*(tap/3) - 2;
            int dx = 2*(tap - (tap/3)*3) - 2;
            int crow = (k0 & 127) + lkk;
            int mn = n0 + lcc;
            int m = mn >> 6, n = mn & 63;
            int mp = m + dy;
            bool mok = ((unsigned)mp < 64u);
            const float* srow = B + (size_t)crow * 4096 + mp * 64;
            #pragma unroll
            for (int i = 0; i < 4; i++) {
                int np = n + dx + i;
                sB[lkk][lcc + i] = (mok && (unsigned)np < 64u) ? srow[np] : 0.f;
            }
        }
        __syncthreads();
        #pragma unroll
        for (int kk = 0; kk < 8; kk++) {
            float a[8], b[8];
            *(float4*)&a[0] = *(float4*)&sA[kk][ty*8];
            *(float4*)&a[4] = *(float4*)&sA[kk][ty*8 + 4];
            *(float4*)&b[0] = *(float4*)&sB[kk][tx*8];
            *(float4*)&b[4] = *(float4*)&sB[kk][tx*8 + 4];
            #pragma unroll
            for (int i = 0; i < 8; i++)
                #pragma unroll
                for (int j = 0; j < 8; j++)
                    acc[i][j] = fmaf(a[i], b[j], acc[i][j]);
        }
        __syncthreads();
    }
    // epilogue
    #pragma unroll
    for (int i = 0; i < 8; i++) {
        int m = m0 + ty*8 + i;
        float bi = RELU ? bias[m] : 0.f;
        float4 v0, v1;
        v0.x = acc[i][0] + bi; v0.y = acc[i][1] + bi; v0.z = acc[i][2] + bi; v0.w = acc[i][3] + bi;
        v1.x = acc[i][4] + bi; v1.y = acc[i][5] + bi; v1.z = acc[i][6] + bi; v1.w = acc[i][7] + bi;
        if (RELU) {
            v0.x = fmaxf(v0.x, 0.f); v0.y = fmaxf(v0.y, 0.f); v0.z = fmaxf(v0.z, 0.f); v0.w = fmaxf(v0.w, 0.f);
            v1.x = fmaxf(v1.x, 0.f); v1.y = fmaxf(v1.y, 0.f); v1.z = fmaxf(v1.z, 0.f); v1.w = fmaxf(v1.w, 0.f);
        }
        *(float4*)&C[(size_t)m * 4096 + n0 + tx*8]     = v0;
        *(float4*)&C[(size_t)m * 4096 + n0 + tx*8 + 4] = v1;
    }
}

// ---------------- radix-select histogram pass ----------------
template<int PASS>
__global__ __launch_bounds__(256) void k_hist() {
    const int NJ = (PASS == 0) ? 1 : 4;
    const int SH = 24 - 8*PASS;
    __shared__ unsigned sh[4][256];
    int tid = threadIdx.x;
    for (int i = tid; i < 1024; i += 256) ((unsigned*)sh)[i] = 0u;
    unsigned pfx[4];
    #pragma unroll
    for (int j = 0; j < 4; j++) pfx[j] = (PASS == 0) ? 0u : g_prefix[j];
    __syncthreads();
    const uint4* __restrict__ src = (const uint4*)g_D;
    int idx = blockIdx.x * 256 + tid;
    const int stride = gridDim.x * 256;
    const int lane = tid & 31;
    for (int i = idx; i < TOTAL/4; i += stride) {
        uint4 u = src[i];
        unsigned vals[4] = {u.x & 0x7fffffffu, u.y & 0x7fffffffu, u.z & 0x7fffffffu, u.w & 0x7fffffffu};
        #pragma unroll
        for (int e = 0; e < 4; e++) {
            unsigned bits = vals[e];
            unsigned byte = (bits >> SH) & 255u;
            #pragma unroll
            for (int j = 0; j < NJ; j++) {
                bool part = true;
                if (PASS > 0) part = ((bits >> (SH + 8)) == (pfx[j] >> (SH + 8)));
                unsigned pm = __ballot_sync(0xffffffffu, part);
                if (part) {
                    unsigned mm = __match_any_sync(pm, byte);
                    int ldr = __ffs(mm) - 1;
                    if (lane == ldr) atomicAdd(&sh[j][byte], (unsigned)__popc(mm));
                }
            }
        }
    }
    __syncthreads();
    for (int i = tid; i < 1024; i += 256) {
        unsigned v = ((unsigned*)sh)[i];
        if (v) atomicAdd(&g_hist[i], v);
    }
}

template<int PASS>
__global__ void k_scan() {
    int j = threadIdx.x;
    if (j < 4) {
        const int SH = 24 - 8*PASS;
        unsigned krem = g_remain[j];
        const unsigned* h = &g_hist[(PASS == 0 ? 0 : j) * 256];
        unsigned cum = 0; int chosen = 0;
        for (int b = 255; b >= 0; b--) {
            unsigned hv = h[b];
            if (cum + hv >= krem) { chosen = b; break; }
            cum += hv;
        }
        g_remain[j] = krem - cum;
        unsigned pfx = g_prefix[j] | ((unsigned)chosen << SH);
        g_prefix[j] = pfx;
        if (PASS == 3) g_thr[j] = __uint_as_float(pfx);
    }
    __syncthreads();
    for (int i = threadIdx.x; i < 1024; i += blockDim.x) g_hist[i] = 0u;
}

// ---------------- softmax over 512 concat channels + residual ----------------
__global__ __launch_bounds__(256) void k_final(const float* __restrict__ x, float* __restrict__ out) {
    int t = blockIdx.x * 256 + threadIdx.x;     // 0..32767
    if (t >= 8*4096) return;
    int b = t >> 12, mn = t & 4095;
    const int obase = b * 524288 + mn;       // g_OUTS batch stride: 128*4096 per branch slab
    const size_t xbase = (size_t)b * 2097152 + mn;  // x/out batch stride: 512*4096
    float mx = -1e30f;
    #pragma unroll 4
    for (int c = 0; c < 512; c++) {
        float v = g_OUTS[(c >> 7) * 4194304 + obase + (c & 127) * 4096];
        mx = fmaxf(mx, v);
    }
    float s = 0.f;
    #pragma unroll 4
    for (int c = 0; c < 512; c++) {
        float v = g_OUTS[(c >> 7) * 4194304 + obase + (c & 127) * 4096];
        s += __expf(v - mx);
    }
    float inv = 1.f / s;
    #pragma unroll 4
    for (int c = 0; c < 512; c++) {
        float v = g_OUTS[(c >> 7) * 4194304 + obase + (c & 127) * 4096];
        float w = __expf(v - mx) * inv;
        float xv = x[xbase + (size_t)c * 4096];
        out[xbase + (size_t)c * 4096] = fmaf(xv, w, xv);
    }
}

// ---------------- launch ----------------
extern "C" void kernel_launch(void* const* d_in, const int* in_sizes, int n_in,
                              void* d_out, int out_size) {
    const float* x  = (const float*)d_in[0];
    const float* W1 = (const float*)d_in[1];
    const float* b1 = (const float*)d_in[2];
    const float* W2 = (const float*)d_in[3];
    const float* b2 = (const float*)d_in[4];
    const float* W3 = (const float*)d_in[5];
    const float* b3 = (const float*)d_in[6];
    float* out = (float*)d_out;

    float *gT, *gD, *gY, *gR, *gH1, *gH2, *gOUTS, *gAk, *gAkT, *gW1T, *gW2T, *gW3T;
    cudaGetSymbolAddress((void**)&gT, g_T);
    cudaGetSymbolAddress((void**)&gD, g_D);
    cudaGetSymbolAddress((void**)&gY, g_Y);
    cudaGetSymbolAddress((void**)&gR, g_R);
    cudaGetSymbolAddress((void**)&gH1, g_H1);
    cudaGetSymbolAddress((void**)&gH2, g_H2);
    cudaGetSymbolAddress((void**)&gOUTS, g_OUTS);
    cudaGetSymbolAddress((void**)&gAk, g_Ak);
    cudaGetSymbolAddress((void**)&gAkT, g_AkT);
    cudaGetSymbolAddress((void**)&gW1T, g_W1T);
    cudaGetSymbolAddress((void**)&gW2T, g_W2T);
    cudaGetSymbolAddress((void**)&gW3T, g_W3T);

    k_init<<<1, 256>>>();
    k_build_mats<<<1024, 256>>>();
    k_w1t<<<(4*128*512 + 255)/256, 256>>>(W1);
    k_w2t<<<(4*128*128*9 + 255)/256, 256>>>(W2);
    k_w3t<<<(4*128*128 + 255)/256, 256>>>(W3);

    // forward MN DCT then C DCT
    k_dct64<0><<<4096, 256>>>(x, gT);
    k_gemm<0,0,0><<<dim3(32,4,8), 256>>>(gAkT, 512, gT, 2097152L, gD, 2097152L, 512, nullptr, 0);

    // exact 4-way radix select of thresholds
    k_hist<0><<<512, 256>>>(); k_scan<0><<<1, 256>>>();
    k_hist<1><<<512, 256>>>(); k_scan<1><<<1, 256>>>();
    k_hist<2><<<512, 256>>>(); k_scan<2><<<1, 256>>>();
    k_hist<3><<<512, 256>>>(); k_scan<3><<<1, 256>>>();

    // per-branch: masked inverse + conv stack
    for (int j = 0; j < 4; j++) {
        k_gemm<1,0,0><<<dim3(32,4,8), 256>>>(gAk, 512, gD, 2097152L, gY, 2097152L, 512, nullptr, j);
        k_dct64<1><<<4096, 256>>>(gY, gR);
        k_gemm<0,0,1><<<dim3(32,1,8), 256>>>(gW1T + j*65536, 128, gR, 2097152L, gH1, 524288L, 512, b1 + j*128, 0);
        k_gemm<0,1,1><<<dim3(32,1,8), 256>>>(gW2T + j*147456, 128, gH1, 524288L, gH2, 524288L, 1152, b2 + j*128, 0);
        k_gemm<0,0,1><<<dim3(32,1,8), 256>>>(gW3T + j*16384, 128, gH2, 524288L, gOUTS + (size_t)j*4194304, 524288L, 128, b3 + j*128, 0);
    }

    k_final<<<128, 256>>>(x, out);
}

// round 4
// speedup vs baseline: 1.8688x; 1.8688x over previous
#include <cuda_runtime.h>
#include <cuda_bf16.h>
#include <math.h>

typedef __nv_bfloat16 bf16;
#define TOTAL 16777216   // 8*512*64*64
#define PI_D 3.14159265358979323846

// ---------------- device scratch ----------------
__device__ float g_Ac[64*64];
__device__ float g_Ak[512*512];
__device__ float g_AkT[512*512];
__device__ float g_T[TOTAL];
__device__ float g_D[TOTAL];
__device__ float g_Y[TOTAL];
__device__ float g_OUTS[TOTAL];          // [j][b][o][mn]
__device__ bf16  g_D16[TOTAL];
__device__ unsigned char g_Lvl[TOTAL];
__device__ bf16  g_R16[TOTAL];
__device__ bf16  g_H1[8*128*4096];
__device__ bf16  g_H2[8*128*4096];
__device__ bf16  g_B2[8*1152*4096];      // im2col-expanded conv2 input
__device__ bf16  g_AkI16[512*512];       // [c][k] = Ak[k][c]
__device__ bf16  g_W1b[4*128*512];       // [j][o][c]
__device__ bf16  g_W2b[4*128*1152];      // [j][o][tap*128+c]
__device__ bf16  g_W3b[4*128*128];       // [j][o][c]
__device__ unsigned g_hist[1024];
__device__ unsigned g_prefix[4];
__device__ unsigned g_remain[4];
__device__ float    g_thr[4];

// ---------------- init ----------------
__global__ void k_init() {
    int t = threadIdx.x;
    if (t < 4) {
        g_prefix[t] = 0u;
        g_remain[t] = (unsigned)(TOTAL >> (2 + 2*t));
    }
    for (int i = t; i < 1024; i += blockDim.x) g_hist[i] = 0u;
}

// ---------------- DCT basis ----------------
__global__ void k_build_mats() {
    int tid = blockIdx.x * blockDim.x + threadIdx.x;
    if (tid < 512*512) {
        int k = tid >> 9, c = tid & 511;
        double v = cos((double)k * ((double)c + 0.5) * (PI_D/512.0)) * sqrt(2.0/512.0);
        if (k == 0) v *= 0.70710678118654752440;
        float f = (float)v;
        g_Ak[k*512 + c]  = f;
        g_AkT[c*512 + k] = f;
        g_AkI16[c*512 + k] = __float2bfloat16(f);   // row-major [c][k]
    }
    if (tid < 4096) {
        int k = tid >> 6, n = tid & 63;
        double v = cos((double)k * ((double)n + 0.5) * (PI_D/64.0)) * sqrt(2.0/64.0);
        if (k == 0) v *= 0.70710678118654752440;
        g_Ac[tid] = (float)v;
    }
}

// ---------------- weight bf16 conversions ----------------
__global__ void k_cvt_w1(const float* __restrict__ W1) {   // [4][128][512] direct
    int i = blockIdx.x * blockDim.x + threadIdx.x;
    if (i < 4*128*512) g_W1b[i] = __float2bfloat16(W1[i]);
}
__global__ void k_cvt_w2(const float* __restrict__ W2) {   // [j][o][c][tap] -> [j][o][tap*128+c]
    int i = blockIdx.x * blockDim.x + threadIdx.x;
    if (i >= 4*128*128*9) return;
    int tap = i % 9;
    int r = i / 9;
    int c = r & 127; r >>= 7;
    int o = r & 127; int j = r >> 7;
    g_W2b[((j*128 + o)*1152) + tap*128 + c] = __float2bfloat16(W2[i]);
}
__global__ void k_cvt_w3(const float* __restrict__ W3) {   // [4][128][128] direct
    int i = blockIdx.x * blockDim.x + threadIdx.x;
    if (i < 4*128*128) g_W3b[i] = __float2bfloat16(W3[i]);
}

// ---------------- fused 64x64 two-sided DCT ----------------
__device__ __forceinline__ void st1(float* p, float v) { *p = v; }
__device__ __forceinline__ void st1(bf16* p, float v)  { *p = __float2bfloat16(v); }

template<int INV, typename TO>
__global__ __launch_bounds__(256) void k_dct64(const float* __restrict__ in, TO* __restrict__ out) {
    __shared__ float sA[64*65];
    __shared__ float sX[64*65];
    const int tid = threadIdx.x;
    const float* __restrict__ src = in + (size_t)blockIdx.x * 4096;
    TO* __restrict__ dst = out + (size_t)blockIdx.x * 4096;
    #pragma unroll
    for (int q = 0; q < 16; q++) {
        int e = tid + 256*q;
        int i = e >> 6, c = e & 63;
        sA[i*65 + c] = g_Ac[e];
        sX[i*65 + c] = src[e];
    }
    __syncthreads();
    const int i0 = (tid >> 4) << 2;
    const int j0 = (tid & 15) << 2;
    float q1[4][4];
    #pragma unroll
    for (int a = 0; a < 4; a++)
        #pragma unroll
        for (int b = 0; b < 4; b++) q1[a][b] = 0.f;
    for (int k = 0; k < 64; k++) {
        float av[4], bv[4];
        #pragma unroll
        for (int a = 0; a < 4; a++)
            av[a] = INV ? sA[k*65 + i0 + a] : sA[(i0 + a)*65 + k];
        #pragma unroll
        for (int b = 0; b < 4; b++) bv[b] = sX[k*65 + j0 + b];
        #pragma unroll
        for (int a = 0; a < 4; a++)
            #pragma unroll
            for (int b = 0; b < 4; b++) q1[a][b] = fmaf(av[a], bv[b], q1[a][b]);
    }
    __syncthreads();
    #pragma unroll
    for (int a = 0; a < 4; a++)
        #pragma unroll
        for (int b = 0; b < 4; b++) sX[(i0 + a)*65 + j0 + b] = q1[a][b];
    __syncthreads();
    float q2[4][4];
    #pragma unroll
    for (int a = 0; a < 4; a++)
        #pragma unroll
        for (int b = 0; b < 4; b++) q2[a][b] = 0.f;
    for (int k = 0; k < 64; k++) {
        float av[4], bv[4];
        #pragma unroll
        for (int a = 0; a < 4; a++) av[a] = sX[(i0 + a)*65 + k];
        #pragma unroll
        for (int b = 0; b < 4; b++)
            bv[b] = INV ? sA[k*65 + j0 + b] : sA[(j0 + b)*65 + k];
        #pragma unroll
        for (int a = 0; a < 4; a++)
            #pragma unroll
            for (int b = 0; b < 4; b++) q2[a][b] = fmaf(av[a], bv[b], q2[a][b]);
    }
    #pragma unroll
    for (int a = 0; a < 4; a++)
        #pragma unroll
        for (int b = 0; b < 4; b++)
            st1(&dst[(i0 + a)*64 + j0 + b], q2[a][b]);
}

// ---------------- fp32 SGEMM (forward C-DCT only) ----------------
template<int MASKED, int IM2COL, int RELU>
__global__ __launch_bounds__(256) void k_gemm(
    const float* __restrict__ A, int lda,
    const float* __restrict__ Bbase, long strideB,
    float* __restrict__ Cbase, long strideC,
    int K, const float* __restrict__ bias, int branch)
{
    __shared__ float sA[8][128];
    __shared__ float sB[8][132];
    const float* __restrict__ B = Bbase + (long)blockIdx.z * strideB;
    float* __restrict__ C = Cbase + (long)blockIdx.z * strideC;
    const int m0 = blockIdx.y << 7;
    const int n0 = blockIdx.x << 7;
    const int tid = threadIdx.x;
    const int tx = tid & 15, ty = tid >> 4;
    const int lkk = tid >> 5, lcc = (tid & 31) << 2;
    float acc[8][8];
    #pragma unroll
    for (int i = 0; i < 8; i++)
        #pragma unroll
        for (int j = 0; j < 8; j++) acc[i][j] = 0.f;

    for (int k0 = 0; k0 < K; k0 += 8) {
        float4 av = *(const float4*)&A[(size_t)(k0 + lkk) * lda + m0 + lcc];
        *(float4*)&sA[lkk][lcc] = av;
        float4 bv = *(const float4*)&B[(size_t)(k0 + lkk) * 4096 + n0 + lcc];
        *(float4*)&sB[lkk][lcc] = bv;
        __syncthreads();
        #pragma unroll
        for (int kk = 0; kk < 8; kk++) {
            float a[8], b[8];
            *(float4*)&a[0] = *(float4*)&sA[kk][ty*8];
            *(float4*)&a[4] = *(float4*)&sA[kk][ty*8 + 4];
            *(float4*)&b[0] = *(float4*)&sB[kk][tx*8];
            *(float4*)&b[4] = *(float4*)&sB[kk][tx*8 + 4];
            #pragma unroll
            for (int i = 0; i < 8; i++)
                #pragma unroll
                for (int j = 0; j < 8; j++)
                    acc[i][j] = fmaf(a[i], b[j], acc[i][j]);
        }
        __syncthreads();
    }
    #pragma unroll
    for (int i = 0; i < 8; i++) {
        int m = m0 + ty*8 + i;
        float4 v0 = make_float4(acc[i][0], acc[i][1], acc[i][2], acc[i][3]);
        float4 v1 = make_float4(acc[i][4], acc[i][5], acc[i][6], acc[i][7]);
        *(float4*)&C[(size_t)m * 4096 + n0 + tx*8]     = v0;
        *(float4*)&C[(size_t)m * 4096 + n0 + tx*8 + 4] = v1;
    }
}

// ---------------- bf16 tensor-core GEMM ----------------
// C[m][n] = sum_k A[m][k]*B[k][n];  A bf16 row-major [M][K], B bf16 [K][4096] per z.
// MASKED: zero B elems with level <= branch. OUTBF16: bf16 output. RELU: bias+relu.
template<int MASKED, int OUTBF16, int RELU>
__global__ __launch_bounds__(256) void k_bgemm(
    const bf16* __restrict__ A,
    const bf16* __restrict__ Bbase, long strideB,
    const unsigned char* __restrict__ LvlBase,
    void* __restrict__ Cbase, long strideC,
    int K, const float* __restrict__ bias, int branch)
{
    __shared__ bf16 sA[128*40];    // [m][k] row-major, stride 40 (80B, 16B-aligned rows)
    __shared__ bf16 sBk[32*136];   // [k][n] natural, stride 136 (272B)
    const int tid = threadIdx.x;
    const int warp = tid >> 5, lane = tid & 31;
    const int z = blockIdx.z;
    const bf16* __restrict__ B = Bbase + (long)z * strideB;
    const unsigned char* __restrict__ Lvl = MASKED ? (LvlBase + (long)z * strideB) : (const unsigned char*)0;
    const int m0 = blockIdx.y << 7, n0 = blockIdx.x << 7;
    const int wm = (warp >> 2) * 64;
    const int wn = (warp & 3) * 32;

    // ldmatrix lane addressing
    const int quad = lane >> 3, qr = lane & 7;
    const int a_moff = (quad & 1) * 8 + qr;
    const int a_koff = (quad >> 1) * 8;
    const int bl = lane & 15;
    const int b_koff = ((bl >> 3) << 3) + (bl & 7);

    // gmem load roles
    const int a_r = tid >> 2;            // 0..63 (+64 second pass)
    const int a_kg = (tid & 3) * 8;
    const int b_kr = tid >> 3;           // 0..31
    const int b_ng = (tid & 7) * 16;     // 0..112

    float acc[16][4];
    #pragma unroll
    for (int i = 0; i < 16; i++) { acc[i][0]=0.f; acc[i][1]=0.f; acc[i][2]=0.f; acc[i][3]=0.f; }

    for (int k0 = 0; k0 < K; k0 += 32) {
        // A tile: [128][32] row-major, direct copy
        #pragma unroll
        for (int p = 0; p < 2; p++) {
            int row = a_r + p*64;
            uint4 v = *(const uint4*)&A[(size_t)(m0 + row) * K + k0 + a_kg];
            *(uint4*)&sA[row*40 + a_kg] = v;
        }
        // B tile: [32][128] natural
        {
            int krow = k0 + b_kr;
            const bf16* bp = &B[(size_t)krow * 4096 + n0 + b_ng];
            uint4 v0 = *(const uint4*)bp;
            uint4 v1 = *(const uint4*)(bp + 8);
            if (MASKED) {
                const unsigned char* lp = &Lvl[(size_t)krow * 4096 + n0 + b_ng];
                unsigned long long l0 = *(const unsigned long long*)lp;
                unsigned long long l1 = *(const unsigned long long*)(lp + 8);
                unsigned short* s0 = (unsigned short*)&v0;
                unsigned short* s1 = (unsigned short*)&v1;
                #pragma unroll
                for (int e = 0; e < 8; e++) {
                    if ((int)((l0 >> (8*e)) & 255ull) <= branch) s0[e] = 0;
                    if ((int)((l1 >> (8*e)) & 255ull) <= branch) s1[e] = 0;
                }
            }
            *(uint4*)&sBk[b_kr*136 + b_ng]     = v0;
            *(uint4*)&sBk[b_kr*136 + b_ng + 8] = v1;
        }
        __syncthreads();
        #pragma unroll
        for (int kk = 0; kk < 32; kk += 16) {
            unsigned af[4][4], bfr[4][2];
            #pragma unroll
            for (int mt = 0; mt < 4; mt++) {
                unsigned addr = (unsigned)__cvta_generic_to_shared(
                    &sA[(wm + mt*16 + a_moff)*40 + kk + a_koff]);
                asm volatile("ldmatrix.sync.aligned.m8n8.x4.shared.b16 {%0,%1,%2,%3}, [%4];"
                    : "=r"(af[mt][0]), "=r"(af[mt][1]), "=r"(af[mt][2]), "=r"(af[mt][3])
                    : "r"(addr));
            }
            #pragma unroll
            for (int nt = 0; nt < 4; nt++) {
                unsigned addr = (unsigned)__cvta_generic_to_shared(
                    &sBk[(kk + b_koff)*136 + wn + nt*8]);
                asm volatile("ldmatrix.sync.aligned.m8n8.x2.trans.shared.b16 {%0,%1}, [%2];"
                    : "=r"(bfr[nt][0]), "=r"(bfr[nt][1]) : "r"(addr));
            }
            #pragma unroll
            for (int mt = 0; mt < 4; mt++)
                #pragma unroll
                for (int nt = 0; nt < 4; nt++) {
                    float* c = acc[mt*4 + nt];
                    asm volatile(
                        "mma.sync.aligned.m16n8k16.row.col.f32.bf16.bf16.f32 "
                        "{%0,%1,%2,%3}, {%4,%5,%6,%7}, {%8,%9}, {%0,%1,%2,%3};"
                        : "+f"(c[0]), "+f"(c[1]), "+f"(c[2]), "+f"(c[3])
                        : "r"(af[mt][0]), "r"(af[mt][1]), "r"(af[mt][2]), "r"(af[mt][3]),
                          "r"(bfr[nt][0]), "r"(bfr[nt][1]));
                }
        }
        __syncthreads();
    }
    // epilogue
    const int g = lane >> 2, t = lane & 3;
    #pragma unroll
    for (int mt = 0; mt < 4; mt++) {
        #pragma unroll
        for (int half = 0; half < 2; half++) {
            int mrow = m0 + wm + mt*16 + g + half*8;
            float bi = RELU ? bias[mrow] : 0.f;
            #pragma unroll
            for (int nt = 0; nt < 4; nt++) {
                float v0 = acc[mt*4 + nt][half*2 + 0] + bi;
                float v1 = acc[mt*4 + nt][half*2 + 1] + bi;
                if (RELU) { v0 = fmaxf(v0, 0.f); v1 = fmaxf(v1, 0.f); }
                int col = n0 + wn + nt*8 + t*2;
                if (OUTBF16) {
                    bf16* C = (bf16*)Cbase + (long)z * strideC;
                    unsigned pack = (unsigned)__bfloat16_as_ushort(__float2bfloat16(v0))
                                  | ((unsigned)__bfloat16_as_ushort(__float2bfloat16(v1)) << 16);
                    *(unsigned*)&C[(size_t)mrow * 4096 + col] = pack;
                } else {
                    float* C = (float*)Cbase + (long)z * strideC;
                    *(float2*)&C[(size_t)mrow * 4096 + col] = make_float2(v0, v1);
                }
            }
        }
    }
}

// ---------------- radix-select histogram ----------------
template<int PASS>
__global__ __launch_bounds__(256) void k_hist() {
    const int NJ = (PASS == 0) ? 1 : 4;
    const int SH = 24 - 8*PASS;
    __shared__ unsigned sh[4][256];
    int tid = threadIdx.x;
    for (int i = tid; i < 1024; i += 256) ((unsigned*)sh)[i] = 0u;
    unsigned pfx[4];
    #pragma unroll
    for (int j = 0; j < 4; j++) pfx[j] = (PASS == 0) ? 0u : g_prefix[j];
    __syncthreads();
    const uint4* __restrict__ src = (const uint4*)g_D;
    int idx = blockIdx.x * 256 + tid;
    const int stride = gridDim.x * 256;
    const int lane = tid & 31;
    for (int i = idx; i < TOTAL/4; i += stride) {
        uint4 u = src[i];
        unsigned vals[4] = {u.x & 0x7fffffffu, u.y & 0x7fffffffu, u.z & 0x7fffffffu, u.w & 0x7fffffffu};
        #pragma unroll
        for (int e = 0; e < 4; e++) {
            unsigned bits = vals[e];
            unsigned byte = (bits >> SH) & 255u;
            #pragma unroll
            for (int j = 0; j < NJ; j++) {
                bool part = true;
                if (PASS > 0) part = ((bits >> (SH + 8)) == (pfx[j] >> (SH + 8)));
                unsigned pm = __ballot_sync(0xffffffffu, part);
                if (part) {
                    unsigned mm = __match_any_sync(pm, byte);
                    int ldr = __ffs(mm) - 1;
                    if (lane == ldr) atomicAdd(&sh[j][byte], (unsigned)__popc(mm));
                }
            }
        }
    }
    __syncthreads();
    for (int i = tid; i < 1024; i += 256) {
        unsigned v = ((unsigned*)sh)[i];
        if (v) atomicAdd(&g_hist[i], v);
    }
}

template<int PASS>
__global__ void k_scan() {
    int j = threadIdx.x;
    if (j < 4) {
        const int SH = 24 - 8*PASS;
        unsigned krem = g_remain[j];
        const unsigned* h = &g_hist[(PASS == 0 ? 0 : j) * 256];
        unsigned cum = 0; int chosen = 0;
        for (int b = 255; b >= 0; b--) {
            unsigned hv = h[b];
            if (cum + hv >= krem) { chosen = b; break; }
            cum += hv;
        }
        g_remain[j] = krem - cum;
        unsigned pfx = g_prefix[j] | ((unsigned)chosen << SH);
        g_prefix[j] = pfx;
        if (PASS == 3) g_thr[j] = __uint_as_float(pfx);
    }
    __syncthreads();
    for (int i = threadIdx.x; i < 1024; i += blockDim.x) g_hist[i] = 0u;
}

// ---------------- D -> bf16 copy + per-element mask level ----------------
__global__ __launch_bounds__(256) void k_level() {
    int i = blockIdx.x * 256 + threadIdx.x;   // over TOTAL/4
    float4 v = ((const float4*)g_D)[i];
    float t0 = g_thr[0], t1 = g_thr[1], t2 = g_thr[2], t3 = g_thr[3];
    float vv[4] = {v.x, v.y, v.z, v.w};
    unsigned lv = 0;
    #pragma unroll
    for (int e = 0; e < 4; e++) {
        float a = fabsf(vv[e]);
        unsigned c = (unsigned)(a >= t0) + (unsigned)(a >= t1) + (unsigned)(a >= t2) + (unsigned)(a >= t3);
        lv |= c << (8*e);
    }
    ((unsigned*)g_Lvl)[i] = lv;
    unsigned p0 = (unsigned)__bfloat16_as_ushort(__float2bfloat16(v.x))
                | ((unsigned)__bfloat16_as_ushort(__float2bfloat16(v.y)) << 16);
    unsigned p1 = (unsigned)__bfloat16_as_ushort(__float2bfloat16(v.z))
                | ((unsigned)__bfloat16_as_ushort(__float2bfloat16(v.w)) << 16);
    ((uint2*)g_D16)[i] = make_uint2(p0, p1);
}

// ---------------- im2col expansion for conv2 (dilation 2) ----------------
__global__ __launch_bounds__(256) void k_expand() {
    int t = blockIdx.x * 256 + threadIdx.x;      // tasks of 8 elems: 8*1152*4096/8
    if (t >= 4718592) return;
    int mn0 = (t & 511) * 8;
    int r = t >> 9;                               // (b, k)
    int k = r % 1152;
    int b = r / 1152;
    int tap = k >> 7, c = k & 127;
    int dy = 2*(tap/3) - 2;
    int dx = 2*(tap - (tap/3)*3) - 2;
    int m = mn0 >> 6, n = mn0 & 63;
    int mp = m + dy;
    bf16 vals[8];
    const bf16* src = &g_H1[((size_t)b*128 + c)*4096 + mp*64];
    bool mok = ((unsigned)mp < 64u);
    #pragma unroll
    for (int i = 0; i < 8; i++) {
        int np = n + dx + i;
        vals[i] = (mok && (unsigned)np < 64u) ? src[np] : __float2bfloat16(0.f);
    }
    *(uint4*)&g_B2[((size_t)b*1152 + k)*4096 + mn0] = *(uint4*)vals;
}

// ---------------- softmax over 512 concat channels + residual ----------------
__global__ __launch_bounds__(256) void k_final(const float* __restrict__ x, float* __restrict__ out) {
    int t = blockIdx.x * 256 + threadIdx.x;
    if (t >= 8*4096) return;
    int b = t >> 12, mn = t & 4095;
    const int obase = b * 524288 + mn;
    const size_t xbase = (size_t)b * 2097152 + mn;
    float mx = -1e30f;
    #pragma unroll 4
    for (int c = 0; c < 512; c++) {
        float v = g_OUTS[(c >> 7) * 4194304 + obase + (c & 127) * 4096];
        mx = fmaxf(mx, v);
    }
    float s = 0.f;
    #pragma unroll 4
    for (int c = 0; c < 512; c++) {
        float v = g_OUTS[(c >> 7) * 4194304 + obase + (c & 127) * 4096];
        s += __expf(v - mx);
    }
    float inv = 1.f / s;
    #pragma unroll 4
    for (int c = 0; c < 512; c++) {
        float v = g_OUTS[(c >> 7) * 4194304 + obase + (c & 127) * 4096];
        float w = __expf(v - mx) * inv;
        float xv = x[xbase + (size_t)c * 4096];
        out[xbase + (size_t)c * 4096] = fmaf(xv, w, xv);
    }
}

// ---------------- launch ----------------
extern "C" void kernel_launch(void* const* d_in, const int* in_sizes, int n_in,
                              void* d_out, int out_size) {
    const float* x  = (const float*)d_in[0];
    const float* W1 = (const float*)d_in[1];
    const float* b1 = (const float*)d_in[2];
    const float* W2 = (const float*)d_in[3];
    const float* b2 = (const float*)d_in[4];
    const float* W3 = (const float*)d_in[5];
    const float* b3 = (const float*)d_in[6];
    float* out = (float*)d_out;

    float *gT, *gD, *gY, *gOUTS, *gAkT;
    bf16 *gD16, *gR16, *gH1, *gH2, *gB2, *gAkI, *gW1b, *gW2b, *gW3b;
    unsigned char* gLvl;
    cudaGetSymbolAddress((void**)&gT, g_T);
    cudaGetSymbolAddress((void**)&gD, g_D);
    cudaGetSymbolAddress((void**)&gY, g_Y);
    cudaGetSymbolAddress((void**)&gOUTS, g_OUTS);
    cudaGetSymbolAddress((void**)&gAkT, g_AkT);
    cudaGetSymbolAddress((void**)&gD16, g_D16);
    cudaGetSymbolAddress((void**)&gR16, g_R16);
    cudaGetSymbolAddress((void**)&gH1, g_H1);
    cudaGetSymbolAddress((void**)&gH2, g_H2);
    cudaGetSymbolAddress((void**)&gB2, g_B2);
    cudaGetSymbolAddress((void**)&gAkI, g_AkI16);
    cudaGetSymbolAddress((void**)&gW1b, g_W1b);
    cudaGetSymbolAddress((void**)&gW2b, g_W2b);
    cudaGetSymbolAddress((void**)&gW3b, g_W3b);
    cudaGetSymbolAddress((void**)&gLvl, g_Lvl);

    k_init<<<1, 256>>>();
    k_build_mats<<<1024, 256>>>();
    k_cvt_w1<<<1024, 256>>>(W1);
    k_cvt_w2<<<2304, 256>>>(W2);
    k_cvt_w3<<<256, 256>>>(W3);

    // forward MN DCT then C DCT (fp32 — preserves threshold exactness)
    k_dct64<0, float><<<4096, 256>>>(x, gT);
    k_gemm<0,0,0><<<dim3(32,4,8), 256>>>(gAkT, 512, gT, 2097152L, gD, 2097152L, 512, nullptr, 0);

    // exact 4-way radix select
    k_hist<0><<<512, 256>>>(); k_scan<0><<<1, 256>>>();
    k_hist<1><<<512, 256>>>(); k_scan<1><<<1, 256>>>();
    k_hist<2><<<512, 256>>>(); k_scan<2><<<1, 256>>>();
    k_hist<3><<<512, 256>>>(); k_scan<3><<<1, 256>>>();

    k_level<<<16384, 256>>>();

    // per-branch: masked inverse (tensor core) + conv stack (tensor core)
    for (int j = 0; j < 4; j++) {
        k_bgemm<1,0,0><<<dim3(32,4,8), 256>>>(gAkI, gD16, 2097152L, gLvl, gY, 2097152L, 512, nullptr, j);
        k_dct64<1, bf16><<<4096, 256>>>(gY, gR16);
        k_bgemm<0,1,1><<<dim3(32,1,8), 256>>>(gW1b + j*65536, gR16, 2097152L, nullptr, gH1, 524288L, 512, b1 + j*128, 0);
        k_expand<<<18432, 256>>>();
        k_bgemm<0,1,1><<<dim3(32,1,8), 256>>>(gW2b + j*147456, gB2, 4718592L, nullptr, gH2, 524288L, 1152, b2 + j*128, 0);
        k_bgemm<0,0,1><<<dim3(32,1,8), 256>>>(gW3b + j*16384, gH2, 524288L, nullptr, gOUTS + (size_t)j*4194304, 524288L, 128, b3 + j*128, 0);
    }

    k_final<<<128, 256>>>(x, out);
}

// round 5
// speedup vs baseline: 2.2829x; 1.2216x over previous
#include <cuda_runtime.h>
#include <cuda_bf16.h>
#include <math.h>

typedef __nv_bfloat16 bf16;
#define TOTAL 16777216   // 8*512*64*64
#define PI_D 3.14159265358979323846

// ---------------- device scratch ----------------
__device__ float g_Ac[64*64];
__device__ float g_D[TOTAL];
__device__ float g_Y[TOTAL];
__device__ float g_OUTS[TOTAL];          // [j][b][o][mn]
__device__ bf16  g_T16[TOTAL];
__device__ bf16  g_D16[TOTAL];
__device__ unsigned char g_Lvl[TOTAL];
__device__ bf16  g_R16[TOTAL];
__device__ bf16  g_H1[8*128*4096];
__device__ bf16  g_H2[8*128*4096];
__device__ bf16  g_Ak16[512*512];        // row-major [k][c]   (forward)
__device__ bf16  g_AkI16[512*512];       // row-major [c][k]   (inverse)
__device__ bf16  g_W1b[4*128*512];       // [j][o][c]
__device__ bf16  g_W2b[4*128*1152];      // [j][o][tap*128+c]
__device__ bf16  g_W3b[4*128*128];       // [j][o][c]
__device__ unsigned g_hist[1024];
__device__ unsigned g_prefix[4];
__device__ unsigned g_remain[4];
__device__ float    g_thr[4];

// ---------------- init ----------------
__global__ void k_init() {
    int t = threadIdx.x;
    if (t < 4) {
        g_prefix[t] = 0u;
        g_remain[t] = (unsigned)(TOTAL >> (2 + 2*t));
    }
    for (int i = t; i < 1024; i += blockDim.x) g_hist[i] = 0u;
}

// ---------------- DCT basis ----------------
__global__ void k_build_mats() {
    int tid = blockIdx.x * blockDim.x + threadIdx.x;
    if (tid < 512*512) {
        int k = tid >> 9, c = tid & 511;
        double v = cos((double)k * ((double)c + 0.5) * (PI_D/512.0)) * sqrt(2.0/512.0);
        if (k == 0) v *= 0.70710678118654752440;
        float f = (float)v;
        g_Ak16[k*512 + c]  = __float2bfloat16(f);
        g_AkI16[c*512 + k] = __float2bfloat16(f);
    }
    if (tid < 4096) {
        int k = tid >> 6, n = tid & 63;
        double v = cos((double)k * ((double)n + 0.5) * (PI_D/64.0)) * sqrt(2.0/64.0);
        if (k == 0) v *= 0.70710678118654752440;
        g_Ac[tid] = (float)v;
    }
}

// ---------------- weight bf16 conversions ----------------
__global__ void k_cvt_w1(const float* __restrict__ W1) {
    int i = blockIdx.x * blockDim.x + threadIdx.x;
    if (i < 4*128*512) g_W1b[i] = __float2bfloat16(W1[i]);
}
__global__ void k_cvt_w2(const float* __restrict__ W2) {   // [j][o][c][tap] -> [j][o][tap*128+c]
    int i = blockIdx.x * blockDim.x + threadIdx.x;
    if (i >= 4*128*128*9) return;
    int tap = i % 9;
    int r = i / 9;
    int c = r & 127; r >>= 7;
    int o = r & 127; int j = r >> 7;
    g_W2b[((j*128 + o)*1152) + tap*128 + c] = __float2bfloat16(W2[i]);
}
__global__ void k_cvt_w3(const float* __restrict__ W3) {
    int i = blockIdx.x * blockDim.x + threadIdx.x;
    if (i < 4*128*128) g_W3b[i] = __float2bfloat16(W3[i]);
}

// ---------------- fused 64x64 two-sided DCT ----------------
__device__ __forceinline__ void st1(float* p, float v) { *p = v; }
__device__ __forceinline__ void st1(bf16* p, float v)  { *p = __float2bfloat16(v); }

template<int INV, typename TO>
__global__ __launch_bounds__(256) void k_dct64(const float* __restrict__ in, TO* __restrict__ out) {
    __shared__ float sA[64*65];
    __shared__ float sX[64*65];
    const int tid = threadIdx.x;
    const float* __restrict__ src = in + (size_t)blockIdx.x * 4096;
    TO* __restrict__ dst = out + (size_t)blockIdx.x * 4096;
    #pragma unroll
    for (int q = 0; q < 16; q++) {
        int e = tid + 256*q;
        int i = e >> 6, c = e & 63;
        sA[i*65 + c] = g_Ac[e];
        sX[i*65 + c] = src[e];
    }
    __syncthreads();
    const int i0 = (tid >> 4) << 2;
    const int j0 = (tid & 15) << 2;
    float q1[4][4];
    #pragma unroll
    for (int a = 0; a < 4; a++)
        #pragma unroll
        for (int b = 0; b < 4; b++) q1[a][b] = 0.f;
    for (int k = 0; k < 64; k++) {
        float av[4], bv[4];
        #pragma unroll
        for (int a = 0; a < 4; a++)
            av[a] = INV ? sA[k*65 + i0 + a] : sA[(i0 + a)*65 + k];
        #pragma unroll
        for (int b = 0; b < 4; b++) bv[b] = sX[k*65 + j0 + b];
        #pragma unroll
        for (int a = 0; a < 4; a++)
            #pragma unroll
            for (int b = 0; b < 4; b++) q1[a][b] = fmaf(av[a], bv[b], q1[a][b]);
    }
    __syncthreads();
    #pragma unroll
    for (int a = 0; a < 4; a++)
        #pragma unroll
        for (int b = 0; b < 4; b++) sX[(i0 + a)*65 + j0 + b] = q1[a][b];
    __syncthreads();
    float q2[4][4];
    #pragma unroll
    for (int a = 0; a < 4; a++)
        #pragma unroll
        for (int b = 0; b < 4; b++) q2[a][b] = 0.f;
    for (int k = 0; k < 64; k++) {
        float av[4], bv[4];
        #pragma unroll
        for (int a = 0; a < 4; a++) av[a] = sX[(i0 + a)*65 + k];
        #pragma unroll
        for (int b = 0; b < 4; b++)
            bv[b] = INV ? sA[k*65 + j0 + b] : sA[(j0 + b)*65 + k];
        #pragma unroll
        for (int a = 0; a < 4; a++)
            #pragma unroll
            for (int b = 0; b < 4; b++) q2[a][b] = fmaf(av[a], bv[b], q2[a][b]);
    }
    #pragma unroll
    for (int a = 0; a < 4; a++)
        #pragma unroll
        for (int b = 0; b < 4; b++)
            st1(&dst[(i0 + a)*64 + j0 + b], q2[a][b]);
}

// ---------------- bf16 tensor-core GEMM ----------------
// C[m][n] = sum_k A[m][k]*B[k][n];  A bf16 row-major [M][K], B bf16 [K][4096] per z.
// MASKED: zero B elems with level <= branch.
// IM2COL: B is logically [1152][4096] built from H1 [128][4096] with 3x3 dil-2 taps.
template<int MASKED, int OUTBF16, int RELU, int IM2COL>
__global__ __launch_bounds__(256) void k_bgemm(
    const bf16* __restrict__ A,
    const bf16* __restrict__ Bbase, long strideB,
    const unsigned char* __restrict__ LvlBase,
    void* __restrict__ Cbase, long strideC,
    int K, const float* __restrict__ bias, int branch)
{
    __shared__ bf16 sA[128*40];    // [m][k] row-major, stride 40
    __shared__ bf16 sBk[32*136];   // [k][n] natural, stride 136
    const int tid = threadIdx.x;
    const int warp = tid >> 5, lane = tid & 31;
    const int z = blockIdx.z;
    const bf16* __restrict__ B = Bbase + (long)z * strideB;
    const unsigned char* __restrict__ Lvl = MASKED ? (LvlBase + (long)z * strideB) : (const unsigned char*)0;
    const int m0 = blockIdx.y << 7, n0 = blockIdx.x << 7;
    const int wm = (warp >> 2) * 64;
    const int wn = (warp & 3) * 32;

    const int quad = lane >> 3, qr = lane & 7;
    const int a_moff = (quad & 1) * 8 + qr;
    const int a_koff = (quad >> 1) * 8;
    const int bl = lane & 15;
    const int b_koff = ((bl >> 3) << 3) + (bl & 7);

    const int a_r = tid >> 2;
    const int a_kg = (tid & 3) * 8;
    const int b_kr = tid >> 3;           // 0..31
    const int b_ng = (tid & 7) * 16;     // 0..112

    float acc[16][4];
    #pragma unroll
    for (int i = 0; i < 16; i++) { acc[i][0]=0.f; acc[i][1]=0.f; acc[i][2]=0.f; acc[i][3]=0.f; }

    for (int k0 = 0; k0 < K; k0 += 32) {
        // A tile
        #pragma unroll
        for (int p = 0; p < 2; p++) {
            int row = a_r + p*64;
            uint4 v = *(const uint4*)&A[(size_t)(m0 + row) * K + k0 + a_kg];
            *(uint4*)&sA[row*40 + a_kg] = v;
        }
        // B tile
        if (!IM2COL) {
            int krow = k0 + b_kr;
            const bf16* bp = &B[(size_t)krow * 4096 + n0 + b_ng];
            uint4 v0 = *(const uint4*)bp;
            uint4 v1 = *(const uint4*)(bp + 8);
            if (MASKED) {
                const unsigned char* lp = &Lvl[(size_t)krow * 4096 + n0 + b_ng];
                unsigned long long l0 = *(const unsigned long long*)lp;
                unsigned long long l1 = *(const unsigned long long*)(lp + 8);
                unsigned short* s0 = (unsigned short*)&v0;
                unsigned short* s1 = (unsigned short*)&v1;
                #pragma unroll
                for (int e = 0; e < 8; e++) {
                    if ((int)((l0 >> (8*e)) & 255ull) <= branch) s0[e] = 0;
                    if ((int)((l1 >> (8*e)) & 255ull) <= branch) s1[e] = 0;
                }
            }
            *(uint4*)&sBk[b_kr*136 + b_ng]     = v0;
            *(uint4*)&sBk[b_kr*136 + b_ng + 8] = v1;
        } else {
            // logical row k -> tap = k>>7 (const per 32-tile), c = k&127, dilation-2 shift
            int k = k0 + b_kr;
            int tap = k >> 7;
            int c = k & 127;
            int t3 = tap / 3;
            int dy = 2*t3 - 2;
            int dx = 2*(tap - 3*t3) - 2;
            int mn0 = n0 + b_ng;
            int m = mn0 >> 6, n = mn0 & 63;     // n in {0,16,32,48}
            int mp = m + dy;
            bool mok = ((unsigned)mp < 64u);
            const bf16* row = &B[(size_t)c * 4096 + mp * 64];
            uint4 a0 = make_uint4(0,0,0,0), a1 = make_uint4(0,0,0,0);
            unsigned e = 0;
            if (mok) {
                a0 = *(const uint4*)&row[n];
                a1 = *(const uint4*)&row[n + 8];
                if (dx == 2)       { if (n + 16 < 64) e = *(const unsigned*)&row[n + 16]; }
                else if (dx == -2) { if (n > 0)       e = *(const unsigned*)&row[n - 2]; }
            }
            uint4 o0, o1;
            if (dx == 0)      { o0 = a0; o1 = a1; }
            else if (dx == 2) { o0 = make_uint4(a0.y, a0.z, a0.w, a1.x);
                                o1 = make_uint4(a1.y, a1.z, a1.w, e); }
            else              { o0 = make_uint4(e, a0.x, a0.y, a0.z);
                                o1 = make_uint4(a0.w, a1.x, a1.y, a1.z); }
            *(uint4*)&sBk[b_kr*136 + b_ng]     = o0;
            *(uint4*)&sBk[b_kr*136 + b_ng + 8] = o1;
        }
        __syncthreads();
        #pragma unroll
        for (int kk = 0; kk < 32; kk += 16) {
            unsigned af[4][4], bfr[4][2];
            #pragma unroll
            for (int mt = 0; mt < 4; mt++) {
                unsigned addr = (unsigned)__cvta_generic_to_shared(
                    &sA[(wm + mt*16 + a_moff)*40 + kk + a_koff]);
                asm volatile("ldmatrix.sync.aligned.m8n8.x4.shared.b16 {%0,%1,%2,%3}, [%4];"
                    : "=r"(af[mt][0]), "=r"(af[mt][1]), "=r"(af[mt][2]), "=r"(af[mt][3])
                    : "r"(addr));
            }
            #pragma unroll
            for (int nt = 0; nt < 4; nt++) {
                unsigned addr = (unsigned)__cvta_generic_to_shared(
                    &sBk[(kk + b_koff)*136 + wn + nt*8]);
                asm volatile("ldmatrix.sync.aligned.m8n8.x2.trans.shared.b16 {%0,%1}, [%2];"
                    : "=r"(bfr[nt][0]), "=r"(bfr[nt][1]) : "r"(addr));
            }
            #pragma unroll
            for (int mt = 0; mt < 4; mt++)
                #pragma unroll
                for (int nt = 0; nt < 4; nt++) {
                    float* c = acc[mt*4 + nt];
                    asm volatile(
                        "mma.sync.aligned.m16n8k16.row.col.f32.bf16.bf16.f32 "
                        "{%0,%1,%2,%3}, {%4,%5,%6,%7}, {%8,%9}, {%0,%1,%2,%3};"
                        : "+f"(c[0]), "+f"(c[1]), "+f"(c[2]), "+f"(c[3])
                        : "r"(af[mt][0]), "r"(af[mt][1]), "r"(af[mt][2]), "r"(af[mt][3]),
                          "r"(bfr[nt][0]), "r"(bfr[nt][1]));
                }
        }
        __syncthreads();
    }
    const int g = lane >> 2, t = lane & 3;
    #pragma unroll
    for (int mt = 0; mt < 4; mt++) {
        #pragma unroll
        for (int half = 0; half < 2; half++) {
            int mrow = m0 + wm + mt*16 + g + half*8;
            float bi = RELU ? bias[mrow] : 0.f;
            #pragma unroll
            for (int nt = 0; nt < 4; nt++) {
                float v0 = acc[mt*4 + nt][half*2 + 0] + bi;
                float v1 = acc[mt*4 + nt][half*2 + 1] + bi;
                if (RELU) { v0 = fmaxf(v0, 0.f); v1 = fmaxf(v1, 0.f); }
                int col = n0 + wn + nt*8 + t*2;
                if (OUTBF16) {
                    bf16* C = (bf16*)Cbase + (long)z * strideC;
                    unsigned pack = (unsigned)__bfloat16_as_ushort(__float2bfloat16(v0))
                                  | ((unsigned)__bfloat16_as_ushort(__float2bfloat16(v1)) << 16);
                    *(unsigned*)&C[(size_t)mrow * 4096 + col] = pack;
                } else {
                    float* C = (float*)Cbase + (long)z * strideC;
                    *(float2*)&C[(size_t)mrow * 4096 + col] = make_float2(v0, v1);
                }
            }
        }
    }
}

// ---------------- radix-select histogram ----------------
template<int PASS>
__global__ __launch_bounds__(256) void k_hist() {
    const int NJ = (PASS == 0) ? 1 : 4;
    const int SH = 24 - 8*PASS;
    __shared__ unsigned sh[4][256];
    int tid = threadIdx.x;
    for (int i = tid; i < 1024; i += 256) ((unsigned*)sh)[i] = 0u;
    unsigned pfx[4];
    #pragma unroll
    for (int j = 0; j < 4; j++) pfx[j] = (PASS == 0) ? 0u : g_prefix[j];
    __syncthreads();
    const uint4* __restrict__ src = (const uint4*)g_D;
    int idx = blockIdx.x * 256 + tid;
    const int stride = gridDim.x * 256;
    const int lane = tid & 31;
    for (int i = idx; i < TOTAL/4; i += stride) {
        uint4 u = src[i];
        unsigned vals[4] = {u.x & 0x7fffffffu, u.y & 0x7fffffffu, u.z & 0x7fffffffu, u.w & 0x7fffffffu};
        #pragma unroll
        for (int e = 0; e < 4; e++) {
            unsigned bits = vals[e];
            unsigned byte = (bits >> SH) & 255u;
            #pragma unroll
            for (int j = 0; j < NJ; j++) {
                bool part = true;
                if (PASS > 0) part = ((bits >> (SH + 8)) == (pfx[j] >> (SH + 8)));
                unsigned pm = __ballot_sync(0xffffffffu, part);
                if (part) {
                    unsigned mm = __match_any_sync(pm, byte);
                    int ldr = __ffs(mm) - 1;
                    if (lane == ldr) atomicAdd(&sh[j][byte], (unsigned)__popc(mm));
                }
            }
        }
    }
    __syncthreads();
    for (int i = tid; i < 1024; i += 256) {
        unsigned v = ((unsigned*)sh)[i];
        if (v) atomicAdd(&g_hist[i], v);
    }
}

template<int PASS>
__global__ void k_scan() {
    int j = threadIdx.x;
    if (j < 4) {
        const int SH = 24 - 8*PASS;
        unsigned krem = g_remain[j];
        const unsigned* h = &g_hist[(PASS == 0 ? 0 : j) * 256];
        unsigned cum = 0; int chosen = 0;
        for (int b = 255; b >= 0; b--) {
            unsigned hv = h[b];
            if (cum + hv >= krem) { chosen = b; break; }
            cum += hv;
        }
        g_remain[j] = krem - cum;
        unsigned pfx = g_prefix[j] | ((unsigned)chosen << SH);
        g_prefix[j] = pfx;
        if (PASS == 3) g_thr[j] = __uint_as_float(pfx);
    }
    __syncthreads();
    for (int i = threadIdx.x; i < 1024; i += blockDim.x) g_hist[i] = 0u;
}

// ---------------- D -> bf16 copy + per-element mask level ----------------
__global__ __launch_bounds__(256) void k_level() {
    int i = blockIdx.x * 256 + threadIdx.x;
    float4 v = ((const float4*)g_D)[i];
    float t0 = g_thr[0], t1 = g_thr[1], t2 = g_thr[2], t3 = g_thr[3];
    float vv[4] = {v.x, v.y, v.z, v.w};
    unsigned lv = 0;
    #pragma unroll
    for (int e = 0; e < 4; e++) {
        float a = fabsf(vv[e]);
        unsigned c = (unsigned)(a >= t0) + (unsigned)(a >= t1) + (unsigned)(a >= t2) + (unsigned)(a >= t3);
        lv |= c << (8*e);
    }
    ((unsigned*)g_Lvl)[i] = lv;
    unsigned p0 = (unsigned)__bfloat16_as_ushort(__float2bfloat16(v.x))
                | ((unsigned)__bfloat16_as_ushort(__float2bfloat16(v.y)) << 16);
    unsigned p1 = (unsigned)__bfloat16_as_ushort(__float2bfloat16(v.z))
                | ((unsigned)__bfloat16_as_ushort(__float2bfloat16(v.w)) << 16);
    ((uint2*)g_D16)[i] = make_uint2(p0, p1);
}

// ---------------- softmax (no-max: logits are small post-ReLU) + residual ----------------
__global__ __launch_bounds__(256) void k_final(const float* __restrict__ x, float* __restrict__ out) {
    int t = blockIdx.x * 256 + threadIdx.x;
    if (t >= 8*4096) return;
    int b = t >> 12, mn = t & 4095;
    const int obase = b * 524288 + mn;
    const size_t xbase = (size_t)b * 2097152 + mn;
    float s = 0.f;
    #pragma unroll 4
    for (int c = 0; c < 512; c++) {
        float v = g_OUTS[(c >> 7) * 4194304 + obase + (c & 127) * 4096];
        s += __expf(v);
    }
    float inv = 1.f / s;
    #pragma unroll 4
    for (int c = 0; c < 512; c++) {
        float v = g_OUTS[(c >> 7) * 4194304 + obase + (c & 127) * 4096];
        float w = __expf(v) * inv;
        float xv = x[xbase + (size_t)c * 4096];
        out[xbase + (size_t)c * 4096] = fmaf(xv, w, xv);
    }
}

// ---------------- launch ----------------
extern "C" void kernel_launch(void* const* d_in, const int* in_sizes, int n_in,
                              void* d_out, int out_size) {
    const float* x  = (const float*)d_in[0];
    const float* W1 = (const float*)d_in[1];
    const float* b1 = (const float*)d_in[2];
    const float* W2 = (const float*)d_in[3];
    const float* b2 = (const float*)d_in[4];
    const float* W3 = (const float*)d_in[5];
    const float* b3 = (const float*)d_in[6];
    float* out = (float*)d_out;

    float *gD, *gY, *gOUTS;
    bf16 *gT16, *gD16, *gR16, *gH1, *gH2, *gAk16, *gAkI, *gW1b, *gW2b, *gW3b;
    unsigned char* gLvl;
    cudaGetSymbolAddress((void**)&gD, g_D);
    cudaGetSymbolAddress((void**)&gY, g_Y);
    cudaGetSymbolAddress((void**)&gOUTS, g_OUTS);
    cudaGetSymbolAddress((void**)&gT16, g_T16);
    cudaGetSymbolAddress((void**)&gD16, g_D16);
    cudaGetSymbolAddress((void**)&gR16, g_R16);
    cudaGetSymbolAddress((void**)&gH1, g_H1);
    cudaGetSymbolAddress((void**)&gH2, g_H2);
    cudaGetSymbolAddress((void**)&gAk16, g_Ak16);
    cudaGetSymbolAddress((void**)&gAkI, g_AkI16);
    cudaGetSymbolAddress((void**)&gW1b, g_W1b);
    cudaGetSymbolAddress((void**)&gW2b, g_W2b);
    cudaGetSymbolAddress((void**)&gW3b, g_W3b);
    cudaGetSymbolAddress((void**)&gLvl, g_Lvl);

    k_init<<<1, 256>>>();
    k_build_mats<<<1024, 256>>>();
    k_cvt_w1<<<1024, 256>>>(W1);
    k_cvt_w2<<<2304, 256>>>(W2);
    k_cvt_w3<<<256, 256>>>(W3);

    // forward: MN DCT (fp32 math, bf16 out) then C-DCT on tensor cores (fp32 out for select)
    k_dct64<0, bf16><<<4096, 256>>>(x, gT16);
    k_bgemm<0,0,0,0><<<dim3(32,4,8), 256>>>(gAk16, gT16, 2097152L, nullptr, gD, 2097152L, 512, nullptr, 0);

    // exact 4-way radix select
    k_hist<0><<<512, 256>>>(); k_scan<0><<<1, 256>>>();
    k_hist<1><<<512, 256>>>(); k_scan<1><<<1, 256>>>();
    k_hist<2><<<512, 256>>>(); k_scan<2><<<1, 256>>>();
    k_hist<3><<<512, 256>>>(); k_scan<3><<<1, 256>>>();

    k_level<<<16384, 256>>>();

    // per-branch: masked inverse + conv stack (all tensor cores; conv2 im2col fused)
    for (int j = 0; j < 4; j++) {
        k_bgemm<1,0,0,0><<<dim3(32,4,8), 256>>>(gAkI, gD16, 2097152L, gLvl, gY, 2097152L, 512, nullptr, j);
        k_dct64<1, bf16><<<4096, 256>>>(gY, gR16);
        k_bgemm<0,1,1,0><<<dim3(32,1,8), 256>>>(gW1b + j*65536, gR16, 2097152L, nullptr, gH1, 524288L, 512, b1 + j*128, 0);
        k_bgemm<0,1,1,1><<<dim3(32,1,8), 256>>>(gW2b + j*147456, gH1, 524288L, nullptr, gH2, 524288L, 1152, b2 + j*128, 0);
        k_bgemm<0,0,1,0><<<dim3(32,1,8), 256>>>(gW3b + j*16384, gH2, 524288L, nullptr, gOUTS + (size_t)j*4194304, 524288L, 128, b3 + j*128, 0);
    }

    k_final<<<128, 256>>>(x, out);
}

// round 7
// speedup vs baseline: 4.0357x; 1.7678x over previous
#include <cuda_runtime.h>
#include <cuda_bf16.h>
#include <math.h>

typedef __nv_bfloat16 bf16;
#define TOTAL 16777216   // 8*512*64*64
#define PI_D 3.14159265358979323846
#define DCT_SMEM 55296

// ---------------- device scratch ----------------
__device__ bf16  g_Ac16[64*64];          // [i][m] = Ac[i][m]
__device__ bf16  g_AcT16[64*64];         // [i][m] = Ac[m][i]
__device__ bf16  g_Ak16[512*512];        // [k][c]   (forward C)
__device__ bf16  g_AkI16[512*512];       // [c][k]   (inverse C)
__device__ float g_D[TOTAL];             // fp32 D for exact select
__device__ bf16  g_T16[TOTAL];
__device__ bf16  g_D16[TOTAL];
__device__ unsigned char g_Lvl[TOTAL];
__device__ bf16  g_Y16[4*TOTAL];         // [j][b][c][mn]
__device__ bf16  g_R16[4*TOTAL];         // [j][b][c][mn]
__device__ bf16  g_H1[32*128*4096];      // [z=j*8+b][o][mn]
__device__ bf16  g_H2[32*128*4096];
__device__ bf16  g_OUTS16[TOTAL];        // [j][b][o][mn]
__device__ bf16  g_W1b[4*128*512];
__device__ bf16  g_W2b[4*128*1152];      // [j][o][tap*128+c]
__device__ bf16  g_W3b[4*128*128];
__device__ unsigned g_hist[1024];
__device__ unsigned g_prefix[4];
__device__ unsigned g_remain[4];
__device__ float    g_thr[4];

__device__ __forceinline__ unsigned packbf(float a, float b) {
    return (unsigned)__bfloat16_as_ushort(__float2bfloat16(a))
         | ((unsigned)__bfloat16_as_ushort(__float2bfloat16(b)) << 16);
}

// ---------------- init ----------------
__global__ void k_init() {
    int t = threadIdx.x;
    if (t < 4) {
        g_prefix[t] = 0u;
        g_remain[t] = (unsigned)(TOTAL >> (2 + 2*t));
    }
    for (int i = t; i < 1024; i += blockDim.x) g_hist[i] = 0u;
}

// ---------------- DCT basis ----------------
__global__ void k_build_mats() {
    int tid = blockIdx.x * blockDim.x + threadIdx.x;
    if (tid < 512*512) {
        int k = tid >> 9, c = tid & 511;
        double v = cos((double)k * ((double)c + 0.5) * (PI_D/512.0)) * sqrt(2.0/512.0);
        if (k == 0) v *= 0.70710678118654752440;
        float f = (float)v;
        g_Ak16[k*512 + c]  = __float2bfloat16(f);
        g_AkI16[c*512 + k] = __float2bfloat16(f);
    }
    if (tid < 4096) {
        int k = tid >> 6, n = tid & 63;
        double v = cos((double)k * ((double)n + 0.5) * (PI_D/64.0)) * sqrt(2.0/64.0);
        if (k == 0) v *= 0.70710678118654752440;
        bf16 f = __float2bfloat16((float)v);
        g_Ac16[k*64 + n]  = f;   // [i][m] = Ac[i][m]
        g_AcT16[n*64 + k] = f;   // [i][m] = Ac[m][i]
    }
}

// ---------------- weight bf16 conversions ----------------
__global__ void k_cvt_w1(const float* __restrict__ W1) {
    int i = blockIdx.x * blockDim.x + threadIdx.x;
    if (i < 4*128*512) g_W1b[i] = __float2bfloat16(W1[i]);
}
__global__ void k_cvt_w2(const float* __restrict__ W2) {
    int i = blockIdx.x * blockDim.x + threadIdx.x;
    if (i >= 4*128*128*9) return;
    int tap = i % 9;
    int r = i / 9;
    int c = r & 127; r >>= 7;
    int o = r & 127; int j = r >> 7;
    g_W2b[((j*128 + o)*1152) + tap*128 + c] = __float2bfloat16(W2[i]);
}
__global__ void k_cvt_w3(const float* __restrict__ W3) {
    int i = blockIdx.x * blockDim.x + threadIdx.x;
    if (i < 4*128*128) g_W3b[i] = __float2bfloat16(W3[i]);
}

// ---------------- tensor-core fused 64x64 two-sided DCT ----------------
// O = A1 * X * A2 ; A1/A2 passed as row-major bf16 64x64.
// One block: 256 threads = 8 warps = 2 slices x 4 warps (16 rows each).
template<int FP32IN>
__global__ __launch_bounds__(256) void k_dct64_tc(
    const void* __restrict__ vin, bf16* __restrict__ out,
    const bf16* __restrict__ A1g, const bf16* __restrict__ A2g)
{
    extern __shared__ bf16 sm[];
    // layout (elems): A1 0, A2 4608, X 9216 + s*4608, Q 18432 + s*4608 (stride 72)
    const int tid = threadIdx.x;
    #pragma unroll
    for (int it = 0; it < 4; it++) {                 // A1+A2: 1024 uint4
        int f = it*256 + tid;
        int mat = f >> 9, wf = f & 511;
        int row = wf >> 3, colb = (wf & 7) * 8;
        uint4 v = *(const uint4*)((mat ? A2g : A1g) + row*64 + colb);
        *(uint4*)&sm[mat*4608 + row*72 + colb] = v;
    }
    if (FP32IN) {
        const float* xin = (const float*)vin;
        #pragma unroll
        for (int it = 0; it < 8; it++) {             // 2048 float4
            int f = it*256 + tid;
            int s = f >> 10, wf = f & 1023;
            int row = wf >> 4, colf = (wf & 15) * 4;
            float4 v = *(const float4*)(xin + (size_t)(blockIdx.x*2 + s)*4096 + row*64 + colf);
            *(uint2*)&sm[9216 + s*4608 + row*72 + colf] =
                make_uint2(packbf(v.x, v.y), packbf(v.z, v.w));
        }
    } else {
        const bf16* yin = (const bf16*)vin;
        #pragma unroll
        for (int it = 0; it < 4; it++) {             // 1024 uint4
            int f = it*256 + tid;
            int s = f >> 9, wf = f & 511;
            int row = wf >> 3, colb = (wf & 7) * 8;
            uint4 v = *(const uint4*)(yin + (size_t)(blockIdx.x*2 + s)*4096 + row*64 + colb);
            *(uint4*)&sm[9216 + s*4608 + row*72 + colb] = v;
        }
    }
    __syncthreads();

    const int warp = tid >> 5, lane = tid & 31;
    const int s = warp >> 2, wrow = (warp & 3) * 16;
    bf16* mX = sm + 9216 + s*4608;
    bf16* mQ = sm + 18432 + s*4608;
    const int quad = lane >> 3, qr = lane & 7;
    const int a_moff = (quad & 1)*8 + qr;
    const int a_koff = (quad >> 1)*8;
    const int b_koff = lane & 15;
    const int g = lane >> 2, t4 = lane & 3;

    float acc[8][4];
    unsigned afA[4][4];

    // ---- stage 1: Q = A1 x X ----
    #pragma unroll
    for (int i = 0; i < 8; i++) { acc[i][0]=0.f; acc[i][1]=0.f; acc[i][2]=0.f; acc[i][3]=0.f; }
    #pragma unroll
    for (int kk = 0; kk < 4; kk++) {
        unsigned addr = (unsigned)__cvta_generic_to_shared(&sm[(wrow + a_moff)*72 + kk*16 + a_koff]);
        asm volatile("ldmatrix.sync.aligned.m8n8.x4.shared.b16 {%0,%1,%2,%3}, [%4];"
            : "=r"(afA[kk][0]), "=r"(afA[kk][1]), "=r"(afA[kk][2]), "=r"(afA[kk][3]) : "r"(addr));
    }
    #pragma unroll
    for (int kk = 0; kk < 4; kk++)
        #pragma unroll
        for (int nt = 0; nt < 8; nt++) {
            unsigned b0, b1;
            unsigned addr = (unsigned)__cvta_generic_to_shared(&mX[(kk*16 + b_koff)*72 + nt*8]);
            asm volatile("ldmatrix.sync.aligned.m8n8.x2.trans.shared.b16 {%0,%1}, [%2];"
                : "=r"(b0), "=r"(b1) : "r"(addr));
            float* c = acc[nt];
            asm volatile(
                "mma.sync.aligned.m16n8k16.row.col.f32.bf16.bf16.f32 "
                "{%0,%1,%2,%3}, {%4,%5,%6,%7}, {%8,%9}, {%0,%1,%2,%3};"
                : "+f"(c[0]), "+f"(c[1]), "+f"(c[2]), "+f"(c[3])
                : "r"(afA[kk][0]), "r"(afA[kk][1]), "r"(afA[kk][2]), "r"(afA[kk][3]),
                  "r"(b0), "r"(b1));
        }
    #pragma unroll
    for (int nt = 0; nt < 8; nt++)
        #pragma unroll
        for (int h = 0; h < 2; h++) {
            int row = wrow + g + h*8, col = nt*8 + t4*2;
            *(unsigned*)&mQ[row*72 + col] = packbf(acc[nt][h*2], acc[nt][h*2+1]);
        }
    __syncwarp();

    // ---- stage 2: O = Q x A2 ----
    #pragma unroll
    for (int i = 0; i < 8; i++) { acc[i][0]=0.f; acc[i][1]=0.f; acc[i][2]=0.f; acc[i][3]=0.f; }
    #pragma unroll
    for (int kk = 0; kk < 4; kk++) {
        unsigned addr = (unsigned)__cvta_generic_to_shared(&mQ[(wrow + a_moff)*72 + kk*16 + a_koff]);
        asm volatile("ldmatrix.sync.aligned.m8n8.x4.shared.b16 {%0,%1,%2,%3}, [%4];"
            : "=r"(afA[kk][0]), "=r"(afA[kk][1]), "=r"(afA[kk][2]), "=r"(afA[kk][3]) : "r"(addr));
    }
    #pragma unroll
    for (int kk = 0; kk < 4; kk++)
        #pragma unroll
        for (int nt = 0; nt < 8; nt++) {
            unsigned b0, b1;
            unsigned addr = (unsigned)__cvta_generic_to_shared(&sm[4608 + (kk*16 + b_koff)*72 + nt*8]);
            asm volatile("ldmatrix.sync.aligned.m8n8.x2.trans.shared.b16 {%0,%1}, [%2];"
                : "=r"(b0), "=r"(b1) : "r"(addr));
            float* c = acc[nt];
            asm volatile(
                "mma.sync.aligned.m16n8k16.row.col.f32.bf16.bf16.f32 "
                "{%0,%1,%2,%3}, {%4,%5,%6,%7}, {%8,%9}, {%0,%1,%2,%3};"
                : "+f"(c[0]), "+f"(c[1]), "+f"(c[2]), "+f"(c[3])
                : "r"(afA[kk][0]), "r"(afA[kk][1]), "r"(afA[kk][2]), "r"(afA[kk][3]),
                  "r"(b0), "r"(b1));
        }
    bf16* dst = out + (size_t)(blockIdx.x*2 + s)*4096;
    #pragma unroll
    for (int nt = 0; nt < 8; nt++)
        #pragma unroll
        for (int h = 0; h < 2; h++) {
            int row = wrow + g + h*8, col = nt*8 + t4*2;
            *(unsigned*)&dst[row*64 + col] = packbf(acc[nt][h*2], acc[nt][h*2+1]);
        }
}

// ---------------- bf16 tensor-core GEMM ----------------
// C[m][n] = sum_k A[m][k]*B[k][n]; B is [K][4096] per z-slab.
// BATCH4: z = j*8+b, j = z>>3 selects A-slab/bias/mask-branch. BMOD8: B-slab index = z&7.
template<int MASKED, int OUTBF16, int RELU, int IM2COL, int BATCH4, int BMOD8>
__global__ __launch_bounds__(256) void k_bgemm(
    const bf16* __restrict__ Abase, long strideAj,
    const bf16* __restrict__ Bbase, long strideB,
    const unsigned char* __restrict__ LvlBase,
    void* __restrict__ Cbase, long strideC,
    int K, const float* __restrict__ bias, int branch)
{
    __shared__ bf16 sA[128*40];
    __shared__ bf16 sBk[32*136];
    const int tid = threadIdx.x;
    const int warp = tid >> 5, lane = tid & 31;
    const int z = blockIdx.z;
    const int jj = BATCH4 ? (z >> 3) : 0;
    const int zb = BMOD8 ? (z & 7) : z;
    const int br = BATCH4 ? jj : branch;
    const bf16* __restrict__ A = Abase + (long)jj * strideAj;
    const bf16* __restrict__ B = Bbase + (long)zb * strideB;
    const unsigned char* __restrict__ Lvl = MASKED ? (LvlBase + (long)zb * strideB) : (const unsigned char*)0;
    const int m0 = blockIdx.y << 7, n0 = blockIdx.x << 7;
    const int wm = (warp >> 2) * 64;
    const int wn = (warp & 3) * 32;

    const int quad = lane >> 3, qr = lane & 7;
    const int a_moff = (quad & 1) * 8 + qr;
    const int a_koff = (quad >> 1) * 8;
    const int b_koff = lane & 15;

    const int a_r = tid >> 2;
    const int a_kg = (tid & 3) * 8;
    const int b_kr = tid >> 3;
    const int b_ng = (tid & 7) * 16;

    float acc[16][4];
    #pragma unroll
    for (int i = 0; i < 16; i++) { acc[i][0]=0.f; acc[i][1]=0.f; acc[i][2]=0.f; acc[i][3]=0.f; }

    for (int k0 = 0; k0 < K; k0 += 32) {
        #pragma unroll
        for (int p = 0; p < 2; p++) {
            int row = a_r + p*64;
            uint4 v = *(const uint4*)&A[(size_t)(m0 + row) * K + k0 + a_kg];
            *(uint4*)&sA[row*40 + a_kg] = v;
        }
        if (!IM2COL) {
            int krow = k0 + b_kr;
            const bf16* bp = &B[(size_t)krow * 4096 + n0 + b_ng];
            uint4 v0 = *(const uint4*)bp;
            uint4 v1 = *(const uint4*)(bp + 8);
            if (MASKED) {
                const unsigned char* lp = &Lvl[(size_t)krow * 4096 + n0 + b_ng];
                unsigned long long l0 = *(const unsigned long long*)lp;
                unsigned long long l1 = *(const unsigned long long*)(lp + 8);
                unsigned short* s0 = (unsigned short*)&v0;
                unsigned short* s1 = (unsigned short*)&v1;
                #pragma unroll
                for (int e = 0; e < 8; e++) {
                    if ((int)((l0 >> (8*e)) & 255ull) <= br) s0[e] = 0;
                    if ((int)((l1 >> (8*e)) & 255ull) <= br) s1[e] = 0;
                }
            }
            *(uint4*)&sBk[b_kr*136 + b_ng]     = v0;
            *(uint4*)&sBk[b_kr*136 + b_ng + 8] = v1;
        } else {
            int k = k0 + b_kr;
            int tap = k >> 7;
            int c = k & 127;
            int t3 = tap / 3;
            int dy = 2*t3 - 2;
            int dx = 2*(tap - 3*t3) - 2;
            int mn0 = n0 + b_ng;
            int m = mn0 >> 6, n = mn0 & 63;
            int mp = m + dy;
            bool mok = ((unsigned)mp < 64u);
            const bf16* row = &B[(size_t)c * 4096 + mp * 64];
            uint4 a0 = make_uint4(0,0,0,0), a1 = make_uint4(0,0,0,0);
            unsigned e = 0;
            if (mok) {
                a0 = *(const uint4*)&row[n];
                a1 = *(const uint4*)&row[n + 8];
                if (dx == 2)       { if (n + 16 < 64) e = *(const unsigned*)&row[n + 16]; }
                else if (dx == -2) { if (n > 0)       e = *(const unsigned*)&row[n - 2]; }
            }
            uint4 o0, o1;
            if (dx == 0)      { o0 = a0; o1 = a1; }
            else if (dx == 2) { o0 = make_uint4(a0.y, a0.z, a0.w, a1.x);
                                o1 = make_uint4(a1.y, a1.z, a1.w, e); }
            else              { o0 = make_uint4(e, a0.x, a0.y, a0.z);
                                o1 = make_uint4(a0.w, a1.x, a1.y, a1.z); }
            *(uint4*)&sBk[b_kr*136 + b_ng]     = o0;
            *(uint4*)&sBk[b_kr*136 + b_ng + 8] = o1;
        }
        __syncthreads();
        #pragma unroll
        for (int kk = 0; kk < 32; kk += 16) {
            unsigned af[4][4], bfr[4][2];
            #pragma unroll
            for (int mt = 0; mt < 4; mt++) {
                unsigned addr = (unsigned)__cvta_generic_to_shared(
                    &sA[(wm + mt*16 + a_moff)*40 + kk + a_koff]);
                asm volatile("ldmatrix.sync.aligned.m8n8.x4.shared.b16 {%0,%1,%2,%3}, [%4];"
                    : "=r"(af[mt][0]), "=r"(af[mt][1]), "=r"(af[mt][2]), "=r"(af[mt][3])
                    : "r"(addr));
            }
            #pragma unroll
            for (int nt = 0; nt < 4; nt++) {
                unsigned addr = (unsigned)__cvta_generic_to_shared(
                    &sBk[(kk + b_koff)*136 + wn + nt*8]);
                asm volatile("ldmatrix.sync.aligned.m8n8.x2.trans.shared.b16 {%0,%1}, [%2];"
                    : "=r"(bfr[nt][0]), "=r"(bfr[nt][1]) : "r"(addr));
            }
            #pragma unroll
            for (int mt = 0; mt < 4; mt++)
                #pragma unroll
                for (int nt = 0; nt < 4; nt++) {
                    float* c = acc[mt*4 + nt];
                    asm volatile(
                        "mma.sync.aligned.m16n8k16.row.col.f32.bf16.bf16.f32 "
                        "{%0,%1,%2,%3}, {%4,%5,%6,%7}, {%8,%9}, {%0,%1,%2,%3};"
                        : "+f"(c[0]), "+f"(c[1]), "+f"(c[2]), "+f"(c[3])
                        : "r"(af[mt][0]), "r"(af[mt][1]), "r"(af[mt][2]), "r"(af[mt][3]),
                          "r"(bfr[nt][0]), "r"(bfr[nt][1]));
                }
        }
        __syncthreads();
    }
    const int g = lane >> 2, t = lane & 3;
    #pragma unroll
    for (int mt = 0; mt < 4; mt++) {
        #pragma unroll
        for (int half = 0; half < 2; half++) {
            int mrow = m0 + wm + mt*16 + g + half*8;
            float bi = RELU ? bias[jj*128 + mrow] : 0.f;
            #pragma unroll
            for (int nt = 0; nt < 4; nt++) {
                float v0 = acc[mt*4 + nt][half*2 + 0] + bi;
                float v1 = acc[mt*4 + nt][half*2 + 1] + bi;
                if (RELU) { v0 = fmaxf(v0, 0.f); v1 = fmaxf(v1, 0.f); }
                int col = n0 + wn + nt*8 + t*2;
                if (OUTBF16) {
                    bf16* C = (bf16*)Cbase + (long)z * strideC;
                    *(unsigned*)&C[(size_t)mrow * 4096 + col] = packbf(v0, v1);
                } else {
                    float* C = (float*)Cbase + (long)z * strideC;
                    *(float2*)&C[(size_t)mrow * 4096 + col] = make_float2(v0, v1);
                }
            }
        }
    }
}

// ---------------- radix-select pass 0 (match-aggregated: exponent bins collide) ----------------
__global__ __launch_bounds__(256) void k_hist0() {
    __shared__ unsigned sh[256];
    int tid = threadIdx.x;
    sh[tid] = 0u;
    __syncthreads();
    const uint4* __restrict__ src = (const uint4*)g_D;
    int idx = blockIdx.x * 256 + tid;
    const int stride = gridDim.x * 256;
    const int lane = tid & 31;
    for (int i = idx; i < TOTAL/4; i += stride) {
        uint4 u = src[i];
        unsigned vals[4] = {u.x & 0x7fffffffu, u.y & 0x7fffffffu, u.z & 0x7fffffffu, u.w & 0x7fffffffu};
        #pragma unroll
        for (int e = 0; e < 4; e++) {
            unsigned byte = vals[e] >> 24;
            unsigned mm = __match_any_sync(0xffffffffu, byte);
            if (lane == __ffs(mm) - 1) atomicAdd(&sh[byte], (unsigned)__popc(mm));
        }
    }
    __syncthreads();
    if (sh[tid]) atomicAdd(&g_hist[tid], sh[tid]);
}

// ---------------- radix-select passes 1..3 (sparse participation, plain atomics) ----------------
template<int PASS>
__global__ __launch_bounds__(256) void k_hist2() {
    const int SH = 24 - 8*PASS;
    __shared__ unsigned sh[4][256];
    int tid = threadIdx.x;
    for (int i = tid; i < 1024; i += 256) ((unsigned*)sh)[i] = 0u;
    __syncthreads();
    unsigned ph[4];
    #pragma unroll
    for (int j = 0; j < 4; j++) ph[j] = g_prefix[j] >> (SH + 8);
    const uint4* __restrict__ src = (const uint4*)g_D;
    int idx = blockIdx.x * 256 + tid;
    const int stride = gridDim.x * 256;
    for (int i = idx; i < TOTAL/4; i += stride) {
        uint4 u = src[i];
        unsigned vals[4] = {u.x & 0x7fffffffu, u.y & 0x7fffffffu, u.z & 0x7fffffffu, u.w & 0x7fffffffu};
        #pragma unroll
        for (int e = 0; e < 4; e++) {
            unsigned bits = vals[e];
            unsigned hi = bits >> (SH + 8);
            unsigned byte = (bits >> SH) & 255u;
            #pragma unroll
            for (int j = 0; j < 4; j++)
                if (hi == ph[j]) atomicAdd(&sh[j][byte], 1u);
        }
    }
    __syncthreads();
    for (int i = tid; i < 1024; i += 256) {
        unsigned v = ((unsigned*)sh)[i];
        if (v) atomicAdd(&g_hist[i], v);
    }
}

template<int PASS>
__global__ void k_scan() {
    int j = threadIdx.x;
    if (j < 4) {
        const int SH = 24 - 8*PASS;
        unsigned krem = g_remain[j];
        const unsigned* h = &g_hist[(PASS == 0 ? 0 : j) * 256];
        unsigned cum = 0; int chosen = 0;
        for (int b = 255; b >= 0; b--) {
            unsigned hv = h[b];
            if (cum + hv >= krem) { chosen = b; break; }
            cum += hv;
        }
        g_remain[j] = krem - cum;
        unsigned pfx = g_prefix[j] | ((unsigned)chosen << SH);
        g_prefix[j] = pfx;
        if (PASS == 3) g_thr[j] = __uint_as_float(pfx);
    }
    __syncthreads();
    for (int i = threadIdx.x; i < 1024; i += blockDim.x) g_hist[i] = 0u;
}

// ---------------- D -> bf16 copy + per-element mask level ----------------
__global__ __launch_bounds__(256) void k_level() {
    int i = blockIdx.x * 256 + threadIdx.x;
    float4 v = ((const float4*)g_D)[i];
    float t0 = g_thr[0], t1 = g_thr[1], t2 = g_thr[2], t3 = g_thr[3];
    float vv[4] = {v.x, v.y, v.z, v.w};
    unsigned lv = 0;
    #pragma unroll
    for (int e = 0; e < 4; e++) {
        float a = fabsf(vv[e]);
        unsigned c = (unsigned)(a >= t0) + (unsigned)(a >= t1) + (unsigned)(a >= t2) + (unsigned)(a >= t3);
        lv |= c << (8*e);
    }
    ((unsigned*)g_Lvl)[i] = lv;
    ((uint2*)g_D16)[i] = make_uint2(packbf(v.x, v.y), packbf(v.z, v.w));
}

// ---------------- softmax (logits bounded post-ReLU) + residual ----------------
__global__ __launch_bounds__(256) void k_final(const float* __restrict__ x, float* __restrict__ out) {
    int t = blockIdx.x * 256 + threadIdx.x;
    if (t >= 8*4096) return;
    int b = t >> 12, mn = t & 4095;
    const int obase = b * 524288 + mn;
    const size_t xbase = (size_t)b * 2097152 + mn;
    float s = 0.f;
    #pragma unroll 4
    for (int c = 0; c < 512; c++) {
        float v = __bfloat162float(g_OUTS16[(c >> 7) * 4194304 + obase + (c & 127) * 4096]);
        s += __expf(v);
    }
    float inv = 1.f / s;
    #pragma unroll 4
    for (int c = 0; c < 512; c++) {
        float v = __bfloat162float(g_OUTS16[(c >> 7) * 4194304 + obase + (c & 127) * 4096]);
        float w = __expf(v) * inv;
        float xv = x[xbase + (size_t)c * 4096];
        out[xbase + (size_t)c * 4096] = fmaf(xv, w, xv);
    }
}

// ---------------- launch ----------------
extern "C" void kernel_launch(void* const* d_in, const int* in_sizes, int n_in,
                              void* d_out, int out_size) {
    const float* x  = (const float*)d_in[0];
    const float* W1 = (const float*)d_in[1];
    const float* b1 = (const float*)d_in[2];
    const float* W2 = (const float*)d_in[3];
    const float* b2 = (const float*)d_in[4];
    const float* W3 = (const float*)d_in[5];
    const float* b3 = (const float*)d_in[6];
    float* out = (float*)d_out;

    float *gD;
    bf16 *gT16, *gD16, *gY16, *gR16, *gH1, *gH2, *gOUTS16;
    bf16 *gAk16, *gAkI, *gAc16, *gAcT16, *gW1b, *gW2b, *gW3b;
    unsigned char* gLvl;
    cudaGetSymbolAddress((void**)&gD, g_D);
    cudaGetSymbolAddress((void**)&gT16, g_T16);
    cudaGetSymbolAddress((void**)&gD16, g_D16);
    cudaGetSymbolAddress((void**)&gY16, g_Y16);
    cudaGetSymbolAddress((void**)&gR16, g_R16);
    cudaGetSymbolAddress((void**)&gH1, g_H1);
    cudaGetSymbolAddress((void**)&gH2, g_H2);
    cudaGetSymbolAddress((void**)&gOUTS16, g_OUTS16);
    cudaGetSymbolAddress((void**)&gAk16, g_Ak16);
    cudaGetSymbolAddress((void**)&gAkI, g_AkI16);
    cudaGetSymbolAddress((void**)&gAc16, g_Ac16);
    cudaGetSymbolAddress((void**)&gAcT16, g_AcT16);
    cudaGetSymbolAddress((void**)&gW1b, g_W1b);
    cudaGetSymbolAddress((void**)&gW2b, g_W2b);
    cudaGetSymbolAddress((void**)&gW3b, g_W3b);
    cudaGetSymbolAddress((void**)&gLvl, g_Lvl);

    cudaFuncSetAttribute(k_dct64_tc<1>, cudaFuncAttributeMaxDynamicSharedMemorySize, DCT_SMEM);
    cudaFuncSetAttribute(k_dct64_tc<0>, cudaFuncAttributeMaxDynamicSharedMemorySize, DCT_SMEM);

    k_init<<<1, 256>>>();
    k_build_mats<<<1024, 256>>>();
    k_cvt_w1<<<1024, 256>>>(W1);
    k_cvt_w2<<<2304, 256>>>(W2);
    k_cvt_w3<<<256, 256>>>(W3);

    // forward: MN DCT (TC) then C-DCT (TC, fp32 out for exact select)
    k_dct64_tc<1><<<2048, 256, DCT_SMEM>>>(x, gT16, gAc16, gAcT16);
    k_bgemm<0,0,0,0,0,0><<<dim3(32,4,8), 256>>>(gAk16, 0L, gT16, 2097152L, nullptr, gD, 2097152L, 512, nullptr, 0);

    // exact 4-way radix select
    k_hist0<<<512, 256>>>();    k_scan<0><<<1, 256>>>();
    k_hist2<1><<<512, 256>>>(); k_scan<1><<<1, 256>>>();
    k_hist2<2><<<512, 256>>>(); k_scan<2><<<1, 256>>>();
    k_hist2<3><<<512, 256>>>(); k_scan<3><<<1, 256>>>();

    k_level<<<16384, 256>>>();

    // all 4 branches batched: masked inverse C, inverse MN DCT, conv stack
    k_bgemm<1,1,0,0,1,1><<<dim3(32,4,32), 256>>>(gAkI, 0L, gD16, 2097152L, gLvl, gY16, 2097152L, 512, nullptr, 0);
    k_dct64_tc<0><<<8192, 256, DCT_SMEM>>>(gY16, gR16, gAcT16, gAc16);
    k_bgemm<0,1,1,0,1,0><<<dim3(32,1,32), 256>>>(gW1b, 65536L, gR16, 2097152L, nullptr, gH1, 524288L, 512, b1, 0);
    k_bgemm<0,1,1,1,1,0><<<dim3(32,1,32), 256>>>(gW2b, 147456L, gH1, 524288L, nullptr, gH2, 524288L, 1152, b2, 0);
    k_bgemm<0,1,1,0,1,0><<<dim3(32,1,32), 256>>>(gW3b, 16384L, gH2, 524288L, nullptr, gOUTS16, 524288L, 128, b3, 0);

    k_final<<<128, 256>>>(x, out);
}

// round 8
// speedup vs baseline: 5.0221x; 1.2444x over previous
#include <cuda_runtime.h>
#include <cuda_bf16.h>
#include <math.h>

typedef __nv_bfloat16 bf16;
#define TOTAL 16777216   // 8*512*64*64
#define PI_D 3.14159265358979323846
#define DCT_SMEM 55296

// ---------------- device scratch ----------------
__device__ bf16  g_Ac16[64*64];
__device__ bf16  g_AcT16[64*64];
__device__ bf16  g_Ak16[512*512];        // [k][c]   (forward C)
__device__ bf16  g_AkI16[512*512];       // [c][k]   (inverse C)
__device__ bf16  g_T16[TOTAL];
__device__ bf16  g_D16[TOTAL];
__device__ bf16  g_Y16[4*TOTAL];
__device__ bf16  g_R16[4*TOTAL];
__device__ bf16  g_H1[32*128*4096];
__device__ bf16  g_H2[32*128*4096];
__device__ bf16  g_OUTS16[TOTAL];        // [j][b][o][mn] logits
__device__ bf16  g_W1b[4*128*512];
__device__ bf16  g_W2b[4*128*1152];
__device__ bf16  g_W3b[4*128*128];
__device__ unsigned g_hist[1024];
__device__ unsigned g_prefix[4];
__device__ unsigned g_remain[4];
__device__ unsigned g_thrbits[4];        // 15-bit bf16 magnitude threshold

__device__ __forceinline__ unsigned packbf(float a, float b) {
    return (unsigned)__bfloat16_as_ushort(__float2bfloat16(a))
         | ((unsigned)__bfloat16_as_ushort(__float2bfloat16(b)) << 16);
}

// FMA-pipe exp for v >= 0 (avoids MUFU): exp(v) = 2^(v*log2e) via poly on fract
__device__ __forceinline__ float fexp(float v) {
    float t = v * 1.44269504f;
    int i = (int)t;                       // v >= 0 -> trunc == floor
    float f = t - (float)i;
    float p = 1.8775767e-3f;
    p = fmaf(p, f, 8.9893397e-3f);
    p = fmaf(p, f, 5.5826318e-2f);
    p = fmaf(p, f, 2.4015361e-1f);
    p = fmaf(p, f, 6.9315307e-1f);
    p = fmaf(p, f, 9.9999989e-1f);
    return p * __int_as_float((i + 127) << 23);
}

// ---------------- init ----------------
__global__ void k_init() {
    int t = threadIdx.x;
    if (t < 4) {
        g_prefix[t] = 0u;
        g_remain[t] = (unsigned)(TOTAL >> (2 + 2*t));
    }
    for (int i = t; i < 1024; i += blockDim.x) g_hist[i] = 0u;
}

// ---------------- DCT basis ----------------
__global__ void k_build_mats() {
    int tid = blockIdx.x * blockDim.x + threadIdx.x;
    if (tid < 512*512) {
        int k = tid >> 9, c = tid & 511;
        double v = cos((double)k * ((double)c + 0.5) * (PI_D/512.0)) * sqrt(2.0/512.0);
        if (k == 0) v *= 0.70710678118654752440;
        float f = (float)v;
        g_Ak16[k*512 + c]  = __float2bfloat16(f);
        g_AkI16[c*512 + k] = __float2bfloat16(f);
    }
    if (tid < 4096) {
        int k = tid >> 6, n = tid & 63;
        double v = cos((double)k * ((double)n + 0.5) * (PI_D/64.0)) * sqrt(2.0/64.0);
        if (k == 0) v *= 0.70710678118654752440;
        bf16 f = __float2bfloat16((float)v);
        g_Ac16[k*64 + n]  = f;
        g_AcT16[n*64 + k] = f;
    }
}

// ---------------- weight bf16 conversions ----------------
__global__ void k_cvt_w1(const float* __restrict__ W1) {
    int i = blockIdx.x * blockDim.x + threadIdx.x;
    if (i < 4*128*512) g_W1b[i] = __float2bfloat16(W1[i]);
}
__global__ void k_cvt_w2(const float* __restrict__ W2) {
    int i = blockIdx.x * blockDim.x + threadIdx.x;
    if (i >= 4*128*128*9) return;
    int tap = i % 9;
    int r = i / 9;
    int c = r & 127; r >>= 7;
    int o = r & 127; int j = r >> 7;
    g_W2b[((j*128 + o)*1152) + tap*128 + c] = __float2bfloat16(W2[i]);
}
__global__ void k_cvt_w3(const float* __restrict__ W3) {
    int i = blockIdx.x * blockDim.x + threadIdx.x;
    if (i < 4*128*128) g_W3b[i] = __float2bfloat16(W3[i]);
}

// ---------------- tensor-core fused 64x64 two-sided DCT ----------------
template<int FP32IN>
__global__ __launch_bounds__(256) void k_dct64_tc(
    const void* __restrict__ vin, bf16* __restrict__ out,
    const bf16* __restrict__ A1g, const bf16* __restrict__ A2g)
{
    extern __shared__ bf16 sm[];
    const int tid = threadIdx.x;
    #pragma unroll
    for (int it = 0; it < 4; it++) {
        int f = it*256 + tid;
        int mat = f >> 9, wf = f & 511;
        int row = wf >> 3, colb = (wf & 7) * 8;
        uint4 v = *(const uint4*)((mat ? A2g : A1g) + row*64 + colb);
        *(uint4*)&sm[mat*4608 + row*72 + colb] = v;
    }
    if (FP32IN) {
        const float* xin = (const float*)vin;
        #pragma unroll
        for (int it = 0; it < 8; it++) {
            int f = it*256 + tid;
            int s = f >> 10, wf = f & 1023;
            int row = wf >> 4, colf = (wf & 15) * 4;
            float4 v = *(const float4*)(xin + (size_t)(blockIdx.x*2 + s)*4096 + row*64 + colf);
            *(uint2*)&sm[9216 + s*4608 + row*72 + colf] =
                make_uint2(packbf(v.x, v.y), packbf(v.z, v.w));
        }
    } else {
        const bf16* yin = (const bf16*)vin;
        #pragma unroll
        for (int it = 0; it < 4; it++) {
            int f = it*256 + tid;
            int s = f >> 9, wf = f & 511;
            int row = wf >> 3, colb = (wf & 7) * 8;
            uint4 v = *(const uint4*)(yin + (size_t)(blockIdx.x*2 + s)*4096 + row*64 + colb);
            *(uint4*)&sm[9216 + s*4608 + row*72 + colb] = v;
        }
    }
    __syncthreads();

    const int warp = tid >> 5, lane = tid & 31;
    const int s = warp >> 2, wrow = (warp & 3) * 16;
    bf16* mX = sm + 9216 + s*4608;
    bf16* mQ = sm + 18432 + s*4608;
    const int quad = lane >> 3, qr = lane & 7;
    const int a_moff = (quad & 1)*8 + qr;
    const int a_koff = (quad >> 1)*8;
    const int b_koff = lane & 15;
    const int g = lane >> 2, t4 = lane & 3;

    float acc[8][4];
    unsigned afA[4][4];

    #pragma unroll
    for (int i = 0; i < 8; i++) { acc[i][0]=0.f; acc[i][1]=0.f; acc[i][2]=0.f; acc[i][3]=0.f; }
    #pragma unroll
    for (int kk = 0; kk < 4; kk++) {
        unsigned addr = (unsigned)__cvta_generic_to_shared(&sm[(wrow + a_moff)*72 + kk*16 + a_koff]);
        asm volatile("ldmatrix.sync.aligned.m8n8.x4.shared.b16 {%0,%1,%2,%3}, [%4];"
            : "=r"(afA[kk][0]), "=r"(afA[kk][1]), "=r"(afA[kk][2]), "=r"(afA[kk][3]) : "r"(addr));
    }
    #pragma unroll
    for (int kk = 0; kk < 4; kk++)
        #pragma unroll
        for (int nt = 0; nt < 8; nt++) {
            unsigned b0, b1;
            unsigned addr = (unsigned)__cvta_generic_to_shared(&mX[(kk*16 + b_koff)*72 + nt*8]);
            asm volatile("ldmatrix.sync.aligned.m8n8.x2.trans.shared.b16 {%0,%1}, [%2];"
                : "=r"(b0), "=r"(b1) : "r"(addr));
            float* c = acc[nt];
            asm volatile(
                "mma.sync.aligned.m16n8k16.row.col.f32.bf16.bf16.f32 "
                "{%0,%1,%2,%3}, {%4,%5,%6,%7}, {%8,%9}, {%0,%1,%2,%3};"
                : "+f"(c[0]), "+f"(c[1]), "+f"(c[2]), "+f"(c[3])
                : "r"(afA[kk][0]), "r"(afA[kk][1]), "r"(afA[kk][2]), "r"(afA[kk][3]),
                  "r"(b0), "r"(b1));
        }
    #pragma unroll
    for (int nt = 0; nt < 8; nt++)
        #pragma unroll
        for (int h = 0; h < 2; h++) {
            int row = wrow + g + h*8, col = nt*8 + t4*2;
            *(unsigned*)&mQ[row*72 + col] = packbf(acc[nt][h*2], acc[nt][h*2+1]);
        }
    __syncwarp();

    #pragma unroll
    for (int i = 0; i < 8; i++) { acc[i][0]=0.f; acc[i][1]=0.f; acc[i][2]=0.f; acc[i][3]=0.f; }
    #pragma unroll
    for (int kk = 0; kk < 4; kk++) {
        unsigned addr = (unsigned)__cvta_generic_to_shared(&mQ[(wrow + a_moff)*72 + kk*16 + a_koff]);
        asm volatile("ldmatrix.sync.aligned.m8n8.x4.shared.b16 {%0,%1,%2,%3}, [%4];"
            : "=r"(afA[kk][0]), "=r"(afA[kk][1]), "=r"(afA[kk][2]), "=r"(afA[kk][3]) : "r"(addr));
    }
    #pragma unroll
    for (int kk = 0; kk < 4; kk++)
        #pragma unroll
        for (int nt = 0; nt < 8; nt++) {
            unsigned b0, b1;
            unsigned addr = (unsigned)__cvta_generic_to_shared(&sm[4608 + (kk*16 + b_koff)*72 + nt*8]);
            asm volatile("ldmatrix.sync.aligned.m8n8.x2.trans.shared.b16 {%0,%1}, [%2];"
                : "=r"(b0), "=r"(b1) : "r"(addr));
            float* c = acc[nt];
            asm volatile(
                "mma.sync.aligned.m16n8k16.row.col.f32.bf16.bf16.f32 "
                "{%0,%1,%2,%3}, {%4,%5,%6,%7}, {%8,%9}, {%0,%1,%2,%3};"
                : "+f"(c[0]), "+f"(c[1]), "+f"(c[2]), "+f"(c[3])
                : "r"(afA[kk][0]), "r"(afA[kk][1]), "r"(afA[kk][2]), "r"(afA[kk][3]),
                  "r"(b0), "r"(b1));
        }
    bf16* dst = out + (size_t)(blockIdx.x*2 + s)*4096;
    #pragma unroll
    for (int nt = 0; nt < 8; nt++)
        #pragma unroll
        for (int h = 0; h < 2; h++) {
            int row = wrow + g + h*8, col = nt*8 + t4*2;
            *(unsigned*)&dst[row*64 + col] = packbf(acc[nt][h*2], acc[nt][h*2+1]);
        }
}

// ---------------- bf16 tensor-core GEMM, double-buffered ----------------
// C[m][n] = sum_k A[m][k]*B[k][n]; B is [K][4096] per z-slab.
// MASKED: zero B elems whose bf16 magnitude < g_thrbits[branch].
template<int MASKED, int RELU, int IM2COL, int BATCH4, int BMOD8>
__global__ __launch_bounds__(256) void k_bgemm(
    const bf16* __restrict__ Abase, long strideAj,
    const bf16* __restrict__ Bbase, long strideB,
    bf16* __restrict__ Cbase, long strideC,
    int K, const float* __restrict__ bias)
{
    __shared__ bf16 sA[2][128*40];
    __shared__ bf16 sB[2][32*136];
    const int tid = threadIdx.x;
    const int warp = tid >> 5, lane = tid & 31;
    const int z = blockIdx.z;
    const int jj = BATCH4 ? (z >> 3) : 0;
    const int zb = BMOD8 ? (z & 7) : z;
    const bf16* __restrict__ A = Abase + (long)jj * strideAj;
    const bf16* __restrict__ B = Bbase + (long)zb * strideB;
    const int m0 = blockIdx.y << 7, n0 = blockIdx.x << 7;
    const int wm = (warp >> 2) * 64;
    const int wn = (warp & 3) * 32;
    const unsigned thr = MASKED ? g_thrbits[jj] : 0u;

    const int quad = lane >> 3, qr = lane & 7;
    const int a_moff = (quad & 1) * 8 + qr;
    const int a_koff = (quad >> 1) * 8;
    const int b_koff = lane & 15;

    const int a_r = tid >> 2;
    const int a_kg = (tid & 3) * 8;
    const int b_kr = tid >> 3;
    const int b_ng = (tid & 7) * 16;

    float acc[16][4];
    #pragma unroll
    for (int i = 0; i < 16; i++) { acc[i][0]=0.f; acc[i][1]=0.f; acc[i][2]=0.f; acc[i][3]=0.f; }

    uint4 rA0, rA1, rB0, rB1;

    auto loadTile = [&](int k0) {
        rA0 = *(const uint4*)&A[(size_t)(m0 + a_r) * K + k0 + a_kg];
        rA1 = *(const uint4*)&A[(size_t)(m0 + a_r + 64) * K + k0 + a_kg];
        if (!IM2COL) {
            int krow = k0 + b_kr;
            const bf16* bp = &B[(size_t)krow * 4096 + n0 + b_ng];
            rB0 = *(const uint4*)bp;
            rB1 = *(const uint4*)(bp + 8);
            if (MASKED) {
                unsigned short* s0 = (unsigned short*)&rB0;
                unsigned short* s1 = (unsigned short*)&rB1;
                #pragma unroll
                for (int e = 0; e < 8; e++) {
                    if ((unsigned)(s0[e] & 0x7fff) < thr) s0[e] = 0;
                    if ((unsigned)(s1[e] & 0x7fff) < thr) s1[e] = 0;
                }
            }
        } else {
            int k = k0 + b_kr;
            int tap = k >> 7;
            int c = k & 127;
            int t3 = tap / 3;
            int dy = 2*t3 - 2;
            int dx = 2*(tap - 3*t3) - 2;
            int mn0 = n0 + b_ng;
            int m = mn0 >> 6, n = mn0 & 63;
            int mp = m + dy;
            bool mok = ((unsigned)mp < 64u);
            const bf16* row = &B[(size_t)c * 4096 + mp * 64];
            uint4 a0 = make_uint4(0,0,0,0), a1 = make_uint4(0,0,0,0);
            unsigned e = 0;
            if (mok) {
                a0 = *(const uint4*)&row[n];
                a1 = *(const uint4*)&row[n + 8];
                if (dx == 2)       { if (n + 16 < 64) e = *(const unsigned*)&row[n + 16]; }
                else if (dx == -2) { if (n > 0)       e = *(const unsigned*)&row[n - 2]; }
            }
            if (dx == 0)      { rB0 = a0; rB1 = a1; }
            else if (dx == 2) { rB0 = make_uint4(a0.y, a0.z, a0.w, a1.x);
                                rB1 = make_uint4(a1.y, a1.z, a1.w, e); }
            else              { rB0 = make_uint4(e, a0.x, a0.y, a0.z);
                                rB1 = make_uint4(a0.w, a1.x, a1.y, a1.z); }
        }
    };
    auto storeTile = [&](int buf) {
        *(uint4*)&sA[buf][a_r*40 + a_kg]        = rA0;
        *(uint4*)&sA[buf][(a_r + 64)*40 + a_kg] = rA1;
        *(uint4*)&sB[buf][b_kr*136 + b_ng]      = rB0;
        *(uint4*)&sB[buf][b_kr*136 + b_ng + 8]  = rB1;
    };

    const int ntiles = K >> 5;
    loadTile(0);
    storeTile(0);
    __syncthreads();

    for (int t = 0; t < ntiles; t++) {
        const int buf = t & 1;
        if (t + 1 < ntiles) loadTile((t + 1) << 5);
        #pragma unroll
        for (int kk = 0; kk < 32; kk += 16) {
            unsigned af[4][4], bfr[4][2];
            #pragma unroll
            for (int mt = 0; mt < 4; mt++) {
                unsigned addr = (unsigned)__cvta_generic_to_shared(
                    &sA[buf][(wm + mt*16 + a_moff)*40 + kk + a_koff]);
                asm volatile("ldmatrix.sync.aligned.m8n8.x4.shared.b16 {%0,%1,%2,%3}, [%4];"
                    : "=r"(af[mt][0]), "=r"(af[mt][1]), "=r"(af[mt][2]), "=r"(af[mt][3])
                    : "r"(addr));
            }
            #pragma unroll
            for (int nt = 0; nt < 4; nt++) {
                unsigned addr = (unsigned)__cvta_generic_to_shared(
                    &sB[buf][(kk + b_koff)*136 + wn + nt*8]);
                asm volatile("ldmatrix.sync.aligned.m8n8.x2.trans.shared.b16 {%0,%1}, [%2];"
                    : "=r"(bfr[nt][0]), "=r"(bfr[nt][1]) : "r"(addr));
            }
            #pragma unroll
            for (int mt = 0; mt < 4; mt++)
                #pragma unroll
                for (int nt = 0; nt < 4; nt++) {
                    float* c = acc[mt*4 + nt];
                    asm volatile(
                        "mma.sync.aligned.m16n8k16.row.col.f32.bf16.bf16.f32 "
                        "{%0,%1,%2,%3}, {%4,%5,%6,%7}, {%8,%9}, {%0,%1,%2,%3};"
                        : "+f"(c[0]), "+f"(c[1]), "+f"(c[2]), "+f"(c[3])
                        : "r"(af[mt][0]), "r"(af[mt][1]), "r"(af[mt][2]), "r"(af[mt][3]),
                          "r"(bfr[nt][0]), "r"(bfr[nt][1]));
                }
        }
        if (t + 1 < ntiles) storeTile(buf ^ 1);
        __syncthreads();
    }

    const int g = lane >> 2, t = lane & 3;
    bf16* C = Cbase + (long)z * strideC;
    #pragma unroll
    for (int mt = 0; mt < 4; mt++) {
        #pragma unroll
        for (int half = 0; half < 2; half++) {
            int mrow = m0 + wm + mt*16 + g + half*8;
            float bi = RELU ? bias[jj*128 + mrow] : 0.f;
            #pragma unroll
            for (int nt = 0; nt < 4; nt++) {
                float v0 = acc[mt*4 + nt][half*2 + 0] + bi;
                float v1 = acc[mt*4 + nt][half*2 + 1] + bi;
                if (RELU) { v0 = fmaxf(v0, 0.f); v1 = fmaxf(v1, 0.f); }
                int col = n0 + wn + nt*8 + t*2;
                *(unsigned*)&C[(size_t)mrow * 4096 + col] = packbf(v0, v1);
            }
        }
    }
}

// ---------------- bf16 radix select, pass A: bits [14:7] ----------------
__global__ __launch_bounds__(256) void k_histA() {
    __shared__ unsigned sh[256];
    int tid = threadIdx.x;
    sh[tid] = 0u;
    __syncthreads();
    const uint4* __restrict__ src = (const uint4*)g_D16;
    int idx = blockIdx.x * 256 + tid;
    const int stride = gridDim.x * 256;
    const int lane = tid & 31;
    for (int i = idx; i < TOTAL/8; i += stride) {
        uint4 u = src[i];
        unsigned w[4] = {u.x, u.y, u.z, u.w};
        #pragma unroll
        for (int e = 0; e < 4; e++) {
            unsigned lo = (w[e] & 0x7fffu) >> 7;
            unsigned hi = ((w[e] >> 16) & 0x7fffu) >> 7;
            unsigned mm = __match_any_sync(0xffffffffu, lo);
            if (lane == __ffs(mm) - 1) atomicAdd(&sh[lo], (unsigned)__popc(mm));
            mm = __match_any_sync(0xffffffffu, hi);
            if (lane == __ffs(mm) - 1) atomicAdd(&sh[hi], (unsigned)__popc(mm));
        }
    }
    __syncthreads();
    if (sh[tid]) atomicAdd(&g_hist[tid], sh[tid]);
}

__global__ void k_scanA() {
    int j = threadIdx.x;
    if (j < 4) {
        unsigned krem = g_remain[j];
        unsigned cum = 0; int chosen = 0;
        for (int b = 255; b >= 0; b--) {
            unsigned hv = g_hist[b];
            if (cum + hv >= krem) { chosen = b; break; }
            cum += hv;
        }
        g_remain[j] = krem - cum;
        g_prefix[j] = (unsigned)chosen;
    }
    __syncthreads();
    for (int i = threadIdx.x; i < 1024; i += blockDim.x) g_hist[i] = 0u;
}

// ---------------- pass B: bits [6:0] for the 4 prefixes ----------------
__global__ __launch_bounds__(256) void k_histB() {
    __shared__ unsigned sh[4][128];
    int tid = threadIdx.x;
    for (int i = tid; i < 512; i += 256) ((unsigned*)sh)[i] = 0u;
    __syncthreads();
    unsigned ph[4];
    #pragma unroll
    for (int j = 0; j < 4; j++) ph[j] = g_prefix[j];
    const uint4* __restrict__ src = (const uint4*)g_D16;
    int idx = blockIdx.x * 256 + tid;
    const int stride = gridDim.x * 256;
    for (int i = idx; i < TOTAL/8; i += stride) {
        uint4 u = src[i];
        unsigned w[4] = {u.x, u.y, u.z, u.w};
        #pragma unroll
        for (int e = 0; e < 4; e++) {
            #pragma unroll
            for (int h = 0; h < 2; h++) {
                unsigned mag = ((h ? (w[e] >> 16) : w[e]) & 0x7fffu);
                unsigned hi = mag >> 7, lo = mag & 127u;
                #pragma unroll
                for (int j = 0; j < 4; j++)
                    if (hi == ph[j]) atomicAdd(&sh[j][lo], 1u);
            }
        }
    }
    __syncthreads();
    for (int i = tid; i < 512; i += 256) {
        unsigned v = ((unsigned*)sh)[i];
        if (v) atomicAdd(&g_hist[i], v);
    }
}

__global__ void k_scanB() {
    int j = threadIdx.x;
    if (j < 4) {
        unsigned krem = g_remain[j];
        const unsigned* h = &g_hist[j*128];
        unsigned cum = 0; int chosen = 0;
        for (int b = 127; b >= 0; b--) {
            unsigned hv = h[b];
            if (cum + hv >= krem) { chosen = b; break; }
            cum += hv;
        }
        g_thrbits[j] = (g_prefix[j] << 7) | (unsigned)chosen;
    }
}

// ---------------- softmax (FMA-pipe exp) + residual ----------------
__global__ __launch_bounds__(256) void k_final(const float* __restrict__ x, float* __restrict__ out) {
    int t = blockIdx.x * 256 + threadIdx.x;
    if (t >= 8*4096) return;
    int b = t >> 12, mn = t & 4095;
    const int obase = b * 524288 + mn;
    const size_t xbase = (size_t)b * 2097152 + mn;
    float s = 0.f;
    #pragma unroll 4
    for (int c = 0; c < 512; c++) {
        float v = __bfloat162float(g_OUTS16[(c >> 7) * 4194304 + obase + (c & 127) * 4096]);
        s += fexp(v);
    }
    float inv = 1.f / s;
    #pragma unroll 4
    for (int c = 0; c < 512; c++) {
        float v = __bfloat162float(g_OUTS16[(c >> 7) * 4194304 + obase + (c & 127) * 4096]);
        float w = fexp(v) * inv;
        float xv = x[xbase + (size_t)c * 4096];
        out[xbase + (size_t)c * 4096] = fmaf(xv, w, xv);
    }
}

// ---------------- launch ----------------
extern "C" void kernel_launch(void* const* d_in, const int* in_sizes, int n_in,
                              void* d_out, int out_size) {
    const float* x  = (const float*)d_in[0];
    const float* W1 = (const float*)d_in[1];
    const float* b1 = (const float*)d_in[2];
    const float* W2 = (const float*)d_in[3];
    const float* b2 = (const float*)d_in[4];
    const float* W3 = (const float*)d_in[5];
    const float* b3 = (const float*)d_in[6];
    float* out = (float*)d_out;

    bf16 *gT16, *gD16, *gY16, *gR16, *gH1, *gH2, *gOUTS16;
    bf16 *gAk16, *gAkI, *gAc16, *gAcT16, *gW1b, *gW2b, *gW3b;
    cudaGetSymbolAddress((void**)&gT16, g_T16);
    cudaGetSymbolAddress((void**)&gD16, g_D16);
    cudaGetSymbolAddress((void**)&gY16, g_Y16);
    cudaGetSymbolAddress((void**)&gR16, g_R16);
    cudaGetSymbolAddress((void**)&gH1, g_H1);
    cudaGetSymbolAddress((void**)&gH2, g_H2);
    cudaGetSymbolAddress((void**)&gOUTS16, g_OUTS16);
    cudaGetSymbolAddress((void**)&gAk16, g_Ak16);
    cudaGetSymbolAddress((void**)&gAkI, g_AkI16);
    cudaGetSymbolAddress((void**)&gAc16, g_Ac16);
    cudaGetSymbolAddress((void**)&gAcT16, g_AcT16);
    cudaGetSymbolAddress((void**)&gW1b, g_W1b);
    cudaGetSymbolAddress((void**)&gW2b, g_W2b);
    cudaGetSymbolAddress((void**)&gW3b, g_W3b);

    cudaFuncSetAttribute(k_dct64_tc<1>, cudaFuncAttributeMaxDynamicSharedMemorySize, DCT_SMEM);
    cudaFuncSetAttribute(k_dct64_tc<0>, cudaFuncAttributeMaxDynamicSharedMemorySize, DCT_SMEM);

    k_init<<<1, 256>>>();
    k_build_mats<<<1024, 256>>>();
    k_cvt_w1<<<1024, 256>>>(W1);
    k_cvt_w2<<<2304, 256>>>(W2);
    k_cvt_w3<<<256, 256>>>(W3);

    // forward: MN DCT (TC) then C-DCT (TC) -> D16
    k_dct64_tc<1><<<2048, 256, DCT_SMEM>>>(x, gT16, gAc16, gAcT16);
    k_bgemm<0,0,0,0,0><<<dim3(32,4,8), 256>>>(gAk16, 0L, gT16, 2097152L, gD16, 2097152L, 512, nullptr);

    // 2-pass bf16 radix select (self-consistent with the D16 the inverse consumes)
    k_histA<<<512, 256>>>(); k_scanA<<<1, 256>>>();
    k_histB<<<512, 256>>>(); k_scanB<<<1, 4>>>();

    // all 4 branches batched: masked inverse C, inverse MN DCT, conv stack
    k_bgemm<1,0,0,1,1><<<dim3(32,4,32), 256>>>(gAkI, 0L, gD16, 2097152L, gY16, 2097152L, 512, nullptr);
    k_dct64_tc<0><<<8192, 256, DCT_SMEM>>>(gY16, gR16, gAcT16, gAc16);
    k_bgemm<0,1,0,1,0><<<dim3(32,1,32), 256>>>(gW1b, 65536L, gR16, 2097152L, gH1, 524288L, 512, b1);
    k_bgemm<0,1,1,1,0><<<dim3(32,1,32), 256>>>(gW2b, 147456L, gH1, 524288L, gH2, 524288L, 1152, b2);
    k_bgemm<0,1,0,1,0><<<dim3(32,1,32), 256>>>(gW3b, 16384L, gH2, 524288L, gOUTS16, 524288L, 128, b3);

    k_final<<<128, 256>>>(x, out);
}

// round 9
// speedup vs baseline: 7.6307x; 1.5194x over previous
#include <cuda_runtime.h>
#include <cuda_bf16.h>
#include <math.h>

typedef __nv_bfloat16 bf16;
#define TOTAL 16777216   // 8*512*64*64
#define PI_D 3.14159265358979323846
#define DCT_SMEM 55296

// ---------------- device scratch ----------------
__device__ bf16  g_Ac16[64*64];
__device__ bf16  g_AcT16[64*64];
__device__ bf16  g_Ak16[512*512];        // [k][c]   (forward C)
__device__ bf16  g_AkI16[512*512];       // [c][k]   (inverse C)
__device__ bf16  g_T16[TOTAL];
__device__ bf16  g_D16[TOTAL];
__device__ bf16  g_M1b[4*128*512];       // [j][o][k] = (W1 @ AkI)
__device__ bf16  g_H1pre[32*128*4096];   // conv1 pre-bias, DCT-domain spatial
__device__ bf16  g_H1[32*128*4096];
__device__ bf16  g_H2[32*128*4096];
__device__ bf16  g_OUTS16[TOTAL];        // [j][b][o][mn] logits
__device__ bf16  g_W1b[4*128*512];
__device__ bf16  g_W2b[4*128*1152];
__device__ bf16  g_W3b[4*128*128];
__device__ unsigned g_hist[1024];
__device__ unsigned g_prefix[4];
__device__ unsigned g_remain[4];
__device__ unsigned g_thrbits[4];        // 15-bit bf16 magnitude threshold

__device__ __forceinline__ unsigned packbf(float a, float b) {
    return (unsigned)__bfloat16_as_ushort(__float2bfloat16(a))
         | ((unsigned)__bfloat16_as_ushort(__float2bfloat16(b)) << 16);
}

// FMA-pipe exp for v >= 0: exp(v) = 2^(v*log2e) via poly on fract
__device__ __forceinline__ float fexp(float v) {
    float t = v * 1.44269504f;
    int i = (int)t;
    float f = t - (float)i;
    float p = 1.8775767e-3f;
    p = fmaf(p, f, 8.9893397e-3f);
    p = fmaf(p, f, 5.5826318e-2f);
    p = fmaf(p, f, 2.4015361e-1f);
    p = fmaf(p, f, 6.9315307e-1f);
    p = fmaf(p, f, 9.9999989e-1f);
    return p * __int_as_float((i + 127) << 23);
}

// ---------------- init ----------------
__global__ void k_init() {
    int t = threadIdx.x;
    if (t < 4) {
        g_prefix[t] = 0u;
        g_remain[t] = (unsigned)(TOTAL >> (2 + 2*t));
    }
    for (int i = t; i < 1024; i += blockDim.x) g_hist[i] = 0u;
}

// ---------------- DCT basis ----------------
__global__ void k_build_mats() {
    int tid = blockIdx.x * blockDim.x + threadIdx.x;
    if (tid < 512*512) {
        int k = tid >> 9, c = tid & 511;
        double v = cos((double)k * ((double)c + 0.5) * (PI_D/512.0)) * sqrt(2.0/512.0);
        if (k == 0) v *= 0.70710678118654752440;
        float f = (float)v;
        g_Ak16[k*512 + c]  = __float2bfloat16(f);
        g_AkI16[c*512 + k] = __float2bfloat16(f);
    }
    if (tid < 4096) {
        int k = tid >> 6, n = tid & 63;
        double v = cos((double)k * ((double)n + 0.5) * (PI_D/64.0)) * sqrt(2.0/64.0);
        if (k == 0) v *= 0.70710678118654752440;
        bf16 f = __float2bfloat16((float)v);
        g_Ac16[k*64 + n]  = f;
        g_AcT16[n*64 + k] = f;
    }
}

// ---------------- weight bf16 conversions ----------------
__global__ void k_cvt_w1(const float* __restrict__ W1) {
    int i = blockIdx.x * blockDim.x + threadIdx.x;
    if (i < 4*128*512) g_W1b[i] = __float2bfloat16(W1[i]);
}
__global__ void k_cvt_w2(const float* __restrict__ W2) {
    int i = blockIdx.x * blockDim.x + threadIdx.x;
    if (i >= 4*128*128*9) return;
    int tap = i % 9;
    int r = i / 9;
    int c = r & 127; r >>= 7;
    int o = r & 127; int j = r >> 7;
    g_W2b[((j*128 + o)*1152) + tap*128 + c] = __float2bfloat16(W2[i]);
}
__global__ void k_cvt_w3(const float* __restrict__ W3) {
    int i = blockIdx.x * blockDim.x + threadIdx.x;
    if (i < 4*128*128) g_W3b[i] = __float2bfloat16(W3[i]);
}

// ---------------- tensor-core fused 64x64 two-sided DCT ----------------
// O = A1 * X * A2 ; optional per-slice bias+relu epilogue (bias idx = (slice>>10)*128 + (slice&127))
template<int FP32IN, int BIASRELU>
__global__ __launch_bounds__(256) void k_dct64_tc(
    const void* __restrict__ vin, bf16* __restrict__ out,
    const bf16* __restrict__ A1g, const bf16* __restrict__ A2g,
    const float* __restrict__ bias)
{
    extern __shared__ bf16 sm[];
    const int tid = threadIdx.x;
    #pragma unroll
    for (int it = 0; it < 4; it++) {
        int f = it*256 + tid;
        int mat = f >> 9, wf = f & 511;
        int row = wf >> 3, colb = (wf & 7) * 8;
        uint4 v = *(const uint4*)((mat ? A2g : A1g) + row*64 + colb);
        *(uint4*)&sm[mat*4608 + row*72 + colb] = v;
    }
    if (FP32IN) {
        const float* xin = (const float*)vin;
        #pragma unroll
        for (int it = 0; it < 8; it++) {
            int f = it*256 + tid;
            int s = f >> 10, wf = f & 1023;
            int row = wf >> 4, colf = (wf & 15) * 4;
            float4 v = *(const float4*)(xin + (size_t)(blockIdx.x*2 + s)*4096 + row*64 + colf);
            *(uint2*)&sm[9216 + s*4608 + row*72 + colf] =
                make_uint2(packbf(v.x, v.y), packbf(v.z, v.w));
        }
    } else {
        const bf16* yin = (const bf16*)vin;
        #pragma unroll
        for (int it = 0; it < 4; it++) {
            int f = it*256 + tid;
            int s = f >> 9, wf = f & 511;
            int row = wf >> 3, colb = (wf & 7) * 8;
            uint4 v = *(const uint4*)(yin + (size_t)(blockIdx.x*2 + s)*4096 + row*64 + colb);
            *(uint4*)&sm[9216 + s*4608 + row*72 + colb] = v;
        }
    }
    __syncthreads();

    const int warp = tid >> 5, lane = tid & 31;
    const int s = warp >> 2, wrow = (warp & 3) * 16;
    const int slice = blockIdx.x*2 + s;
    float bi = 0.f;
    if (BIASRELU) bi = bias[(slice >> 10)*128 + (slice & 127)];
    bf16* mX = sm + 9216 + s*4608;
    bf16* mQ = sm + 18432 + s*4608;
    const int quad = lane >> 3, qr = lane & 7;
    const int a_moff = (quad & 1)*8 + qr;
    const int a_koff = (quad >> 1)*8;
    const int b_koff = lane & 15;
    const int g = lane >> 2, t4 = lane & 3;

    float acc[8][4];
    unsigned afA[4][4];

    #pragma unroll
    for (int i = 0; i < 8; i++) { acc[i][0]=0.f; acc[i][1]=0.f; acc[i][2]=0.f; acc[i][3]=0.f; }
    #pragma unroll
    for (int kk = 0; kk < 4; kk++) {
        unsigned addr = (unsigned)__cvta_generic_to_shared(&sm[(wrow + a_moff)*72 + kk*16 + a_koff]);
        asm volatile("ldmatrix.sync.aligned.m8n8.x4.shared.b16 {%0,%1,%2,%3}, [%4];"
            : "=r"(afA[kk][0]), "=r"(afA[kk][1]), "=r"(afA[kk][2]), "=r"(afA[kk][3]) : "r"(addr));
    }
    #pragma unroll
    for (int kk = 0; kk < 4; kk++)
        #pragma unroll
        for (int nt = 0; nt < 8; nt++) {
            unsigned b0, b1;
            unsigned addr = (unsigned)__cvta_generic_to_shared(&mX[(kk*16 + b_koff)*72 + nt*8]);
            asm volatile("ldmatrix.sync.aligned.m8n8.x2.trans.shared.b16 {%0,%1}, [%2];"
                : "=r"(b0), "=r"(b1) : "r"(addr));
            float* c = acc[nt];
            asm volatile(
                "mma.sync.aligned.m16n8k16.row.col.f32.bf16.bf16.f32 "
                "{%0,%1,%2,%3}, {%4,%5,%6,%7}, {%8,%9}, {%0,%1,%2,%3};"
                : "+f"(c[0]), "+f"(c[1]), "+f"(c[2]), "+f"(c[3])
                : "r"(afA[kk][0]), "r"(afA[kk][1]), "r"(afA[kk][2]), "r"(afA[kk][3]),
                  "r"(b0), "r"(b1));
        }
    #pragma unroll
    for (int nt = 0; nt < 8; nt++)
        #pragma unroll
        for (int h = 0; h < 2; h++) {
            int row = wrow + g + h*8, col = nt*8 + t4*2;
            *(unsigned*)&mQ[row*72 + col] = packbf(acc[nt][h*2], acc[nt][h*2+1]);
        }
    __syncwarp();

    #pragma unroll
    for (int i = 0; i < 8; i++) { acc[i][0]=0.f; acc[i][1]=0.f; acc[i][2]=0.f; acc[i][3]=0.f; }
    #pragma unroll
    for (int kk = 0; kk < 4; kk++) {
        unsigned addr = (unsigned)__cvta_generic_to_shared(&mQ[(wrow + a_moff)*72 + kk*16 + a_koff]);
        asm volatile("ldmatrix.sync.aligned.m8n8.x4.shared.b16 {%0,%1,%2,%3}, [%4];"
            : "=r"(afA[kk][0]), "=r"(afA[kk][1]), "=r"(afA[kk][2]), "=r"(afA[kk][3]) : "r"(addr));
    }
    #pragma unroll
    for (int kk = 0; kk < 4; kk++)
        #pragma unroll
        for (int nt = 0; nt < 8; nt++) {
            unsigned b0, b1;
            unsigned addr = (unsigned)__cvta_generic_to_shared(&sm[4608 + (kk*16 + b_koff)*72 + nt*8]);
            asm volatile("ldmatrix.sync.aligned.m8n8.x2.trans.shared.b16 {%0,%1}, [%2];"
                : "=r"(b0), "=r"(b1) : "r"(addr));
            float* c = acc[nt];
            asm volatile(
                "mma.sync.aligned.m16n8k16.row.col.f32.bf16.bf16.f32 "
                "{%0,%1,%2,%3}, {%4,%5,%6,%7}, {%8,%9}, {%0,%1,%2,%3};"
                : "+f"(c[0]), "+f"(c[1]), "+f"(c[2]), "+f"(c[3])
                : "r"(afA[kk][0]), "r"(afA[kk][1]), "r"(afA[kk][2]), "r"(afA[kk][3]),
                  "r"(b0), "r"(b1));
        }
    bf16* dst = out + (size_t)slice*4096;
    #pragma unroll
    for (int nt = 0; nt < 8; nt++)
        #pragma unroll
        for (int h = 0; h < 2; h++) {
            int row = wrow + g + h*8, col = nt*8 + t4*2;
            float v0 = acc[nt][h*2], v1 = acc[nt][h*2+1];
            if (BIASRELU) {
                v0 = fmaxf(v0 + bi, 0.f);
                v1 = fmaxf(v1 + bi, 0.f);
            }
            *(unsigned*)&dst[row*64 + col] = packbf(v0, v1);
        }
}

// ---------------- bf16 tensor-core GEMM, double-buffered ----------------
// C[m][n] = sum_k A[m][k]*B[k][n]; B row stride = ldb, C row stride = ldc.
// z-slab: jj = z >> ZDIV (selects A slab / bias / mask threshold); B slab = (BMOD8 ? z&7 : z)*strideB.
// MASKED: zero B elems whose bf16 magnitude < g_thrbits[jj].
template<int MASKED, int RELU, int IM2COL, int ZDIV, int BMOD8>
__global__ __launch_bounds__(256) void k_bgemm(
    const bf16* __restrict__ Abase, long strideAj,
    const bf16* __restrict__ Bbase, long strideB, int ldb,
    bf16* __restrict__ Cbase, long strideC, int ldc,
    int K, const float* __restrict__ bias)
{
    __shared__ bf16 sA[2][128*40];
    __shared__ bf16 sB[2][32*136];
    const int tid = threadIdx.x;
    const int warp = tid >> 5, lane = tid & 31;
    const int z = blockIdx.z;
    const int jj = z >> ZDIV;
    const int zb = BMOD8 ? (z & 7) : z;
    const bf16* __restrict__ A = Abase + (long)jj * strideAj;
    const bf16* __restrict__ B = Bbase + (long)zb * strideB;
    const int m0 = blockIdx.y << 7, n0 = blockIdx.x << 7;
    const int wm = (warp >> 2) * 64;
    const int wn = (warp & 3) * 32;
    const unsigned thr = MASKED ? g_thrbits[jj] : 0u;

    const int quad = lane >> 3, qr = lane & 7;
    const int a_moff = (quad & 1) * 8 + qr;
    const int a_koff = (quad >> 1) * 8;
    const int b_koff = lane & 15;

    const int a_r = tid >> 2;
    const int a_kg = (tid & 3) * 8;
    const int b_kr = tid >> 3;
    const int b_ng = (tid & 7) * 16;

    float acc[16][4];
    #pragma unroll
    for (int i = 0; i < 16; i++) { acc[i][0]=0.f; acc[i][1]=0.f; acc[i][2]=0.f; acc[i][3]=0.f; }

    uint4 rA0, rA1, rB0, rB1;

    auto loadTile = [&](int k0) {
        rA0 = *(const uint4*)&A[(size_t)(m0 + a_r) * K + k0 + a_kg];
        rA1 = *(const uint4*)&A[(size_t)(m0 + a_r + 64) * K + k0 + a_kg];
        if (!IM2COL) {
            int krow = k0 + b_kr;
            const bf16* bp = &B[(size_t)krow * ldb + n0 + b_ng];
            rB0 = *(const uint4*)bp;
            rB1 = *(const uint4*)(bp + 8);
            if (MASKED) {
                unsigned short* s0 = (unsigned short*)&rB0;
                unsigned short* s1 = (unsigned short*)&rB1;
                #pragma unroll
                for (int e = 0; e < 8; e++) {
                    if ((unsigned)(s0[e] & 0x7fff) < thr) s0[e] = 0;
                    if ((unsigned)(s1[e] & 0x7fff) < thr) s1[e] = 0;
                }
            }
        } else {
            int k = k0 + b_kr;
            int tap = k >> 7;
            int c = k & 127;
            int t3 = tap / 3;
            int dy = 2*t3 - 2;
            int dx = 2*(tap - 3*t3) - 2;
            int mn0 = n0 + b_ng;
            int m = mn0 >> 6, n = mn0 & 63;
            int mp = m + dy;
            bool mok = ((unsigned)mp < 64u);
            const bf16* row = &B[(size_t)c * 4096 + mp * 64];
            uint4 a0 = make_uint4(0,0,0,0), a1 = make_uint4(0,0,0,0);
            unsigned e = 0;
            if (mok) {
                a0 = *(const uint4*)&row[n];
                a1 = *(const uint4*)&row[n + 8];
                if (dx == 2)       { if (n + 16 < 64) e = *(const unsigned*)&row[n + 16]; }
                else if (dx == -2) { if (n > 0)       e = *(const unsigned*)&row[n - 2]; }
            }
            if (dx == 0)      { rB0 = a0; rB1 = a1; }
            else if (dx == 2) { rB0 = make_uint4(a0.y, a0.z, a0.w, a1.x);
                                rB1 = make_uint4(a1.y, a1.z, a1.w, e); }
            else              { rB0 = make_uint4(e, a0.x, a0.y, a0.z);
                                rB1 = make_uint4(a0.w, a1.x, a1.y, a1.z); }
        }
    };
    auto storeTile = [&](int buf) {
        *(uint4*)&sA[buf][a_r*40 + a_kg]        = rA0;
        *(uint4*)&sA[buf][(a_r + 64)*40 + a_kg] = rA1;
        *(uint4*)&sB[buf][b_kr*136 + b_ng]      = rB0;
        *(uint4*)&sB[buf][b_kr*136 + b_ng + 8]  = rB1;
    };

    const int ntiles = K >> 5;
    loadTile(0);
    storeTile(0);
    __syncthreads();

    for (int t = 0; t < ntiles; t++) {
        const int buf = t & 1;
        if (t + 1 < ntiles) loadTile((t + 1) << 5);
        #pragma unroll
        for (int kk = 0; kk < 32; kk += 16) {
            unsigned af[4][4], bfr[4][2];
            #pragma unroll
            for (int mt = 0; mt < 4; mt++) {
                unsigned addr = (unsigned)__cvta_generic_to_shared(
                    &sA[buf][(wm + mt*16 + a_moff)*40 + kk + a_koff]);
                asm volatile("ldmatrix.sync.aligned.m8n8.x4.shared.b16 {%0,%1,%2,%3}, [%4];"
                    : "=r"(af[mt][0]), "=r"(af[mt][1]), "=r"(af[mt][2]), "=r"(af[mt][3])
                    : "r"(addr));
            }
            #pragma unroll
            for (int nt = 0; nt < 4; nt++) {
                unsigned addr = (unsigned)__cvta_generic_to_shared(
                    &sB[buf][(kk + b_koff)*136 + wn + nt*8]);
                asm volatile("ldmatrix.sync.aligned.m8n8.x2.trans.shared.b16 {%0,%1}, [%2];"
                    : "=r"(bfr[nt][0]), "=r"(bfr[nt][1]) : "r"(addr));
            }
            #pragma unroll
            for (int mt = 0; mt < 4; mt++)
                #pragma unroll
                for (int nt = 0; nt < 4; nt++) {
                    float* c = acc[mt*4 + nt];
                    asm volatile(
                        "mma.sync.aligned.m16n8k16.row.col.f32.bf16.bf16.f32 "
                        "{%0,%1,%2,%3}, {%4,%5,%6,%7}, {%8,%9}, {%0,%1,%2,%3};"
                        : "+f"(c[0]), "+f"(c[1]), "+f"(c[2]), "+f"(c[3])
                        : "r"(af[mt][0]), "r"(af[mt][1]), "r"(af[mt][2]), "r"(af[mt][3]),
                          "r"(bfr[nt][0]), "r"(bfr[nt][1]));
                }
        }
        if (t + 1 < ntiles) storeTile(buf ^ 1);
        __syncthreads();
    }

    const int g = lane >> 2, t = lane & 3;
    bf16* C = Cbase + (long)z * strideC;
    #pragma unroll
    for (int mt = 0; mt < 4; mt++) {
        #pragma unroll
        for (int half = 0; half < 2; half++) {
            int mrow = m0 + wm + mt*16 + g + half*8;
            float bi = RELU ? bias[jj*128 + mrow] : 0.f;
            #pragma unroll
            for (int nt = 0; nt < 4; nt++) {
                float v0 = acc[mt*4 + nt][half*2 + 0] + bi;
                float v1 = acc[mt*4 + nt][half*2 + 1] + bi;
                if (RELU) { v0 = fmaxf(v0, 0.f); v1 = fmaxf(v1, 0.f); }
                int col = n0 + wn + nt*8 + t*2;
                *(unsigned*)&C[(size_t)mrow * ldc + col] = packbf(v0, v1);
            }
        }
    }
}

// ---------------- bf16 radix select, pass A: bits [14:7] ----------------
__global__ __launch_bounds__(256) void k_histA() {
    __shared__ unsigned sh[256];
    int tid = threadIdx.x;
    sh[tid] = 0u;
    __syncthreads();
    const uint4* __restrict__ src = (const uint4*)g_D16;
    int idx = blockIdx.x * 256 + tid;
    const int stride = gridDim.x * 256;
    const int lane = tid & 31;
    for (int i = idx; i < TOTAL/8; i += stride) {
        uint4 u = src[i];
        unsigned w[4] = {u.x, u.y, u.z, u.w};
        #pragma unroll
        for (int e = 0; e < 4; e++) {
            unsigned lo = (w[e] & 0x7fffu) >> 7;
            unsigned hi = ((w[e] >> 16) & 0x7fffu) >> 7;
            unsigned mm = __match_any_sync(0xffffffffu, lo);
            if (lane == __ffs(mm) - 1) atomicAdd(&sh[lo], (unsigned)__popc(mm));
            mm = __match_any_sync(0xffffffffu, hi);
            if (lane == __ffs(mm) - 1) atomicAdd(&sh[hi], (unsigned)__popc(mm));
        }
    }
    __syncthreads();
    if (sh[tid]) atomicAdd(&g_hist[tid], sh[tid]);
}

__global__ void k_scanA() {
    int j = threadIdx.x;
    if (j < 4) {
        unsigned krem = g_remain[j];
        unsigned cum = 0; int chosen = 0;
        for (int b = 255; b >= 0; b--) {
            unsigned hv = g_hist[b];
            if (cum + hv >= krem) { chosen = b; break; }
            cum += hv;
        }
        g_remain[j] = krem - cum;
        g_prefix[j] = (unsigned)chosen;
    }
    __syncthreads();
    for (int i = threadIdx.x; i < 1024; i += blockDim.x) g_hist[i] = 0u;
}

// ---------------- pass B: bits [6:0] for the 4 prefixes ----------------
__global__ __launch_bounds__(256) void k_histB() {
    __shared__ unsigned sh[4][128];
    int tid = threadIdx.x;
    for (int i = tid; i < 512; i += 256) ((unsigned*)sh)[i] = 0u;
    __syncthreads();
    unsigned ph[4];
    #pragma unroll
    for (int j = 0; j < 4; j++) ph[j] = g_prefix[j];
    const uint4* __restrict__ src = (const uint4*)g_D16;
    int idx = blockIdx.x * 256 + tid;
    const int stride = gridDim.x * 256;
    for (int i = idx; i < TOTAL/8; i += stride) {
        uint4 u = src[i];
        unsigned w[4] = {u.x, u.y, u.z, u.w};
        #pragma unroll
        for (int e = 0; e < 4; e++) {
            #pragma unroll
            for (int h = 0; h < 2; h++) {
                unsigned mag = ((h ? (w[e] >> 16) : w[e]) & 0x7fffu);
                unsigned hi = mag >> 7, lo = mag & 127u;
                #pragma unroll
                for (int j = 0; j < 4; j++)
                    if (hi == ph[j]) atomicAdd(&sh[j][lo], 1u);
            }
        }
    }
    __syncthreads();
    for (int i = tid; i < 512; i += 256) {
        unsigned v = ((unsigned*)sh)[i];
        if (v) atomicAdd(&g_hist[i], v);
    }
}

__global__ void k_scanB() {
    int j = threadIdx.x;
    if (j < 4) {
        unsigned krem = g_remain[j];
        const unsigned* h = &g_hist[j*128];
        unsigned cum = 0; int chosen = 0;
        for (int b = 127; b >= 0; b--) {
            unsigned hv = h[b];
            if (cum + hv >= krem) { chosen = b; break; }
            cum += hv;
        }
        g_thrbits[j] = (g_prefix[j] << 7) | (unsigned)chosen;
    }
}

// ---------------- softmax (FMA-pipe exp) + residual ----------------
__global__ __launch_bounds__(256) void k_final(const float* __restrict__ x, float* __restrict__ out) {
    int t = blockIdx.x * 256 + threadIdx.x;
    if (t >= 8*4096) return;
    int b = t >> 12, mn = t & 4095;
    const int obase = b * 524288 + mn;
    const size_t xbase = (size_t)b * 2097152 + mn;
    float s = 0.f;
    #pragma unroll 4
    for (int c = 0; c < 512; c++) {
        float v = __bfloat162float(g_OUTS16[(c >> 7) * 4194304 + obase + (c & 127) * 4096]);
        s += fexp(v);
    }
    float inv = 1.f / s;
    #pragma unroll 4
    for (int c = 0; c < 512; c++) {
        float v = __bfloat162float(g_OUTS16[(c >> 7) * 4194304 + obase + (c & 127) * 4096]);
        float w = fexp(v) * inv;
        float xv = x[xbase + (size_t)c * 4096];
        out[xbase + (size_t)c * 4096] = fmaf(xv, w, xv);
    }
}

// ---------------- launch ----------------
extern "C" void kernel_launch(void* const* d_in, const int* in_sizes, int n_in,
                              void* d_out, int out_size) {
    const float* x  = (const float*)d_in[0];
    const float* W1 = (const float*)d_in[1];
    const float* b1 = (const float*)d_in[2];
    const float* W2 = (const float*)d_in[3];
    const float* b2 = (const float*)d_in[4];
    const float* W3 = (const float*)d_in[5];
    const float* b3 = (const float*)d_in[6];
    float* out = (float*)d_out;

    bf16 *gT16, *gD16, *gM1b, *gH1pre, *gH1, *gH2, *gOUTS16;
    bf16 *gAk16, *gAkI, *gAc16, *gAcT16, *gW1b, *gW2b, *gW3b;
    cudaGetSymbolAddress((void**)&gT16, g_T16);
    cudaGetSymbolAddress((void**)&gD16, g_D16);
    cudaGetSymbolAddress((void**)&gM1b, g_M1b);
    cudaGetSymbolAddress((void**)&gH1pre, g_H1pre);
    cudaGetSymbolAddress((void**)&gH1, g_H1);
    cudaGetSymbolAddress((void**)&gH2, g_H2);
    cudaGetSymbolAddress((void**)&gOUTS16, g_OUTS16);
    cudaGetSymbolAddress((void**)&gAk16, g_Ak16);
    cudaGetSymbolAddress((void**)&gAkI, g_AkI16);
    cudaGetSymbolAddress((void**)&gAc16, g_Ac16);
    cudaGetSymbolAddress((void**)&gAcT16, g_AcT16);
    cudaGetSymbolAddress((void**)&gW1b, g_W1b);
    cudaGetSymbolAddress((void**)&gW2b, g_W2b);
    cudaGetSymbolAddress((void**)&gW3b, g_W3b);

    cudaFuncSetAttribute(k_dct64_tc<1,0>, cudaFuncAttributeMaxDynamicSharedMemorySize, DCT_SMEM);
    cudaFuncSetAttribute(k_dct64_tc<0,1>, cudaFuncAttributeMaxDynamicSharedMemorySize, DCT_SMEM);

    k_init<<<1, 256>>>();
    k_build_mats<<<1024, 256>>>();
    k_cvt_w1<<<1024, 256>>>(W1);
    k_cvt_w2<<<2304, 256>>>(W2);
    k_cvt_w3<<<256, 256>>>(W3);

    // M1[j] = W1[j] @ AkI : [128 x 512] per branch (fuses conv1 into the channel inverse)
    k_bgemm<0,0,0,0,0><<<dim3(4,1,4), 256>>>(gW1b, 65536L, gAkI, 0L, 512, gM1b, 65536L, 512, 512, nullptr);

    // forward: MN DCT (TC) then C-DCT (TC) -> D16
    k_dct64_tc<1,0><<<2048, 256, DCT_SMEM>>>(x, gT16, gAc16, gAcT16, nullptr);
    k_bgemm<0,0,0,0,1><<<dim3(32,4,8), 256>>>(gAk16, 0L, gT16, 2097152L, 4096, gD16, 2097152L, 4096, 512, nullptr);

    // 2-pass bf16 radix select (self-consistent with the D16 the inverse consumes)
    k_histA<<<512, 256>>>(); k_scanA<<<1, 256>>>();
    k_histB<<<512, 256>>>(); k_scanB<<<1, 4>>>();

    // masked (inverse-C fused with conv1): H1pre = M1 @ mask(D16), M=128, K=512
    k_bgemm<1,0,0,3,1><<<dim3(32,1,32), 256>>>(gM1b, 65536L, gD16, 2097152L, 4096, gH1pre, 524288L, 4096, 512, nullptr);
    // spatial inverse DCT + bias1 + relu -> H1
    k_dct64_tc<0,1><<<2048, 256, DCT_SMEM>>>(gH1pre, gH1, gAcT16, gAc16, b1);
    // conv2 (im2col fused) and conv3
    k_bgemm<0,1,1,3,0><<<dim3(32,1,32), 256>>>(gW2b, 147456L, gH1, 524288L, 4096, gH2, 524288L, 4096, 1152, b2);
    k_bgemm<0,1,0,3,0><<<dim3(32,1,32), 256>>>(gW3b, 16384L, gH2, 524288L, 4096, gOUTS16, 524288L, 4096, 128, b3);

    k_final<<<128, 256>>>(x, out);
}